// round 12
// baseline (speedup 1.0000x reference)
#include <cuda_runtime.h>
#include <cuda_fp16.h>
#include <math.h>
#include <cstdint>

// Problem constants
#define BB 2
#define SS 4096
#define DD 768
#define HH 12
#define GG 64
#define HD 64
#define WW 256
#define NCC 16
#define NHEADS_S ((size_t)BB * HH * SS * HD)   // 6291456
#define QSCALE (0.125f * 1.4426950408889634f)  // fold log2e: softmax in exp2 domain

// ---------------- scratch (static device globals; no allocation) ----------------
__device__ __half g_xh  [(size_t)BB * SS * DD];      // x fp16, SAME (S,B,D) order as input
__device__ __half g_w16 [7][(size_t)DD * DD];        // W fp16, un-transposed (k,n)
__device__ __half g_qh  [NHEADS_S];                  // [b][h][s][hd], scaled by QSCALE
__device__ __half g_kh  [NHEADS_S];
__device__ __half g_vh  [NHEADS_S];
__device__ __half g_kgh [NHEADS_S];
__device__ __half g_vgh [NHEADS_S];
__device__ __half g_qgh [(size_t)BB * HH * GG * HD];
__device__ __half g_xatth[(size_t)BB * SS * DD];     // attention out, row-major (b,s,d)
__device__ float g_pm   [(size_t)BB * HH * GG * 64];
__device__ float g_pl   [(size_t)BB * HH * GG * 64];
__device__ float g_pacc [(size_t)BB * HH * GG * 64 * HD];

// ---------------- helpers ----------------
__device__ __forceinline__ uint32_t smem_u32(const void* p) {
    uint32_t a;
    asm("{ .reg .u64 t; cvta.to.shared.u64 t, %1; cvt.u32.u64 %0, t; }" : "=r"(a) : "l"(p));
    return a;
}
__device__ __forceinline__ uint32_t packh2(float a, float b) {
    __half2 h = __floats2half2_rn(a, b);
    return *reinterpret_cast<uint32_t*>(&h);
}
// 2^x on the FMA pipe: magic round-to-nearest, degree-4 poly on [-0.5, 0.5]
__device__ __forceinline__ float fexp2(float x) {
    float t = fmaxf(x, -125.0f);
    float r = t + 12582912.0f;
    float fi = r - 12582912.0f;
    float f = t - fi;
    int n = __float_as_int(r) - 0x4B400000;
    float p = 9.61812911e-3f;
    p = fmaf(p, f, 5.55041087e-2f);
    p = fmaf(p, f, 2.40226507e-1f);
    p = fmaf(p, f, 6.93147180e-1f);
    p = fmaf(p, f, 1.0f);
    return __int_as_float((n + 127) << 23) * p;
}
#define CP_ASYNC16(saddr, gptr) \
    asm volatile("cp.async.cg.shared.global [%0], [%1], 16;" :: "r"(saddr), "l"(gptr))
#define CP_COMMIT() asm volatile("cp.async.commit_group;" ::: "memory")
#define CP_WAIT(N)  asm volatile("cp.async.wait_group %0;" :: "n"(N) : "memory")

#define MMA_F16(d, a, b0v, b1v) \
    asm volatile( \
        "mma.sync.aligned.m16n8k16.row.col.f32.f16.f16.f32 " \
        "{%0,%1,%2,%3}, {%4,%5,%6,%7}, {%8,%9}, {%0,%1,%2,%3};" \
        : "+f"((d)[0]), "+f"((d)[1]), "+f"((d)[2]), "+f"((d)[3]) \
        : "r"((a)[0]), "r"((a)[1]), "r"((a)[2]), "r"((a)[3]), \
          "r"(b0v), "r"(b1v))

#define LDSM_X4(r0, r1, r2, r3, addr) \
    asm volatile("ldmatrix.sync.aligned.m8n8.x4.shared.b16 {%0,%1,%2,%3}, [%4];" \
                 : "=r"(r0), "=r"(r1), "=r"(r2), "=r"(r3) : "r"(addr))
#define LDSM_X4_T(r0, r1, r2, r3, addr) \
    asm volatile("ldmatrix.sync.aligned.m8n8.x4.trans.shared.b16 {%0,%1,%2,%3}, [%4];" \
                 : "=r"(r0), "=r"(r1), "=r"(r2), "=r"(r3) : "r"(addr))

// ---------------- elementwise fp32 -> fp16 converts (no transposes) ----------------
// off/cnt in float4 units so the convert can be split across launches.
__global__ void k_cvt_x(const float* __restrict__ src, int off4) {
    size_t t = ((size_t)blockIdx.x * blockDim.x + threadIdx.x + off4) * 4;
    if (t >= (size_t)BB * SS * DD) return;
    float4 v = *(const float4*)(src + t);
    *(uint32_t*)&g_xh[t]     = packh2(v.x, v.y);
    *(uint32_t*)&g_xh[t + 2] = packh2(v.z, v.w);
}
struct W7 { const float* w[7]; };
__global__ void k_cvt_w(W7 p) {
    const float* src = p.w[blockIdx.y];
    __half* dst = g_w16[blockIdx.y];
    size_t t = ((size_t)blockIdx.x * blockDim.x + threadIdx.x) * 4;
    if (t >= (size_t)DD * DD) return;
    float4 v = *(const float4*)(src + t);
    *(uint32_t*)&dst[t]     = packh2(v.x, v.y);
    *(uint32_t*)&dst[t + 2] = packh2(v.z, v.w);
}

// ---------------- fp16 mma.sync GEMM core (128x128, 256 thr, trans-B, 4-stage) ----------------
// A: 128 rows x 32 halves/chunk, stride 80B. B: W direct (k,n): 32 k-rows x 256B,
// stride 272B. 4-stage cp.async, CP_WAIT(2): wait targets load issued 2 chunks back.
#define OPA 10240                 // A bytes per stage (128*80)
#define BSTR 272                  // B row stride bytes
#define STG 19456                 // stage bytes (10240 + 8704, padded)
#define NSTAGE 4
#define SMT (NSTAGE * STG)        // 77824 (dynamic)

__device__ __forceinline__ void gemm_core_h(
    const __half* __restrict__ X, const __half* __restrict__ Wm,
    const float* __restrict__ bias, float* __restrict__ OutF, __half* __restrict__ OutH,
    int in_mode, int out_mode, float scale, char* smem, int m0, int n0)
{
    const uint32_t sbase = smem_u32(smem);
    const int tid = threadIdx.x;
    const int wid = tid >> 5, lane = tid & 31;
    const int wm = (wid >> 2) * 64;
    const int wn = (wid & 3) * 32;
    const int lr = lane >> 2;
    const int lc = lane & 3;
    const int l16 = lane & 15, lh = lane >> 4;
    const int l8 = lane & 7, lb = (lane >> 3) & 1;

    const __half* arow[2];
    const __half* brow[2];
    uint32_t dstoA[2], dstoB[2];
#pragma unroll
    for (int i = 0; i < 2; i++) {
        int li = i * 256 + tid;
        {   // A
            int row = li >> 2, col4 = li & 3;
            int gr = m0 + row;
            int grow;
            if (in_mode == 0)      grow = (gr & 4095) * 2 + (gr >> 12);
            else if (in_mode == 1) grow = (gr & 63) * 2 + (gr >> 6);
            else                   grow = gr;
            arow[i]  = X + (size_t)grow * 768 + col4 * 8;
            dstoA[i] = (uint32_t)(row * 80 + col4 * 16);
        }
        {   // B: row = k (0..31), col16 = n/8 (0..15)
            int row = li >> 4, col16 = li & 15;
            brow[i]  = Wm + (size_t)row * 768 + n0 + col16 * 8;
            dstoB[i] = (uint32_t)(OPA + row * BSTR + col16 * 16);
        }
    }

    float acc[4][4][4];
#pragma unroll
    for (int mt = 0; mt < 4; mt++)
#pragma unroll
        for (int nt = 0; nt < 4; nt++)
#pragma unroll
            for (int e = 0; e < 4; e++) acc[mt][nt][e] = 0.f;

    auto issue = [&](int cc) {
        const int kn = cc * 32;
        const uint32_t st = sbase + (uint32_t)(cc % NSTAGE) * STG;
#pragma unroll
        for (int i = 0; i < 2; i++) {
            CP_ASYNC16(st + dstoA[i], arow[i] + kn);
            CP_ASYNC16(st + dstoB[i], brow[i] + (size_t)kn * 768);
        }
        CP_COMMIT();
    };

    issue(0);
    issue(1);
    issue(2);

    for (int c = 0; c < 24; c++) {
        CP_WAIT(2);
        __syncthreads();
        if (c + 3 < 24) issue(c + 3);

        const uint32_t abase = sbase + (uint32_t)(c % NSTAGE) * STG;
        const uint32_t bbase = abase + OPA;

#pragma unroll
        for (int ks = 0; ks < 2; ks++) {
            const uint32_t koff = (uint32_t)(ks * 16 + lh * 8) * 2;
            uint32_t af[4][4];
#pragma unroll
            for (int mt = 0; mt < 4; mt++)
                LDSM_X4(af[mt][0], af[mt][1], af[mt][2], af[mt][3],
                        abase + (uint32_t)(wm + mt * 16 + l16) * 80 + koff);
            uint32_t bf[2][4];
#pragma unroll
            for (int g2 = 0; g2 < 2; g2++) {
                int krow = ks * 16 + l8 + lb * 8;
                int ncol = wn + g2 * 16 + lh * 8;
                LDSM_X4_T(bf[g2][0], bf[g2][1], bf[g2][2], bf[g2][3],
                          bbase + (uint32_t)(krow * BSTR + ncol * 2));
            }
#pragma unroll
            for (int mt = 0; mt < 4; mt++)
#pragma unroll
                for (int g2 = 0; g2 < 2; g2++) {
                    MMA_F16(acc[mt][2 * g2],     af[mt], bf[g2][0], bf[g2][1]);
                    MMA_F16(acc[mt][2 * g2 + 1], af[mt], bf[g2][2], bf[g2][3]);
                }
        }
        __syncthreads();
    }

#pragma unroll
    for (int mt = 0; mt < 4; mt++) {
#pragma unroll
        for (int half = 0; half < 2; half++) {
            const int rr = m0 + wm + mt * 16 + lr + half * 8;
#pragma unroll
            for (int nt = 0; nt < 4; nt++) {
                const int nn = n0 + wn + nt * 8 + lc * 2;
                float v0 = (acc[mt][nt][half * 2 + 0] + bias[nn])     * scale;
                float v1 = (acc[mt][nt][half * 2 + 1] + bias[nn + 1]) * scale;
                if (out_mode == 1) {
                    int bb = rr >> 12, ss = rr & 4095;
                    *(float2*)(OutF + ((size_t)ss * BB + bb) * DD + nn) = make_float2(v0, v1);
                } else if (out_mode == 0) {
                    int bb = rr >> 12, ss = rr & 4095;
                    int h = nn >> 6, hd0 = nn & 63;
                    *(uint32_t*)(OutH + ((((size_t)bb * HH + h) * SS + ss) * 64 + hd0)) = packh2(v0, v1);
                } else {
                    int bb = rr >> 6, gg2 = rr & 63;
                    int h = nn >> 6, hd0 = nn & 63;
                    *(uint32_t*)(OutH + ((((size_t)bb * HH + h) * GG + gg2) * 64 + hd0)) = packh2(v0, v1);
                }
            }
        }
    }
}

struct Gemm6 { const float* bias[6]; __half* out[6]; float scale[6]; };
__global__ __launch_bounds__(256, 2)
void mma_gemm6(Gemm6 p)
{
    extern __shared__ char smem[];
    const int z = blockIdx.z;
    if (z == 5) {
        if (blockIdx.y != 0) return;
        gemm_core_h(g_xh, g_w16[5], p.bias[5], nullptr, p.out[5], 1, 2, p.scale[5], smem,
                    0, blockIdx.x * 128);
    } else {
        gemm_core_h(g_xh, g_w16[z], p.bias[z], nullptr, p.out[z], 0, 0, p.scale[z], smem,
                    blockIdx.y * 128, blockIdx.x * 128);
    }
}
__global__ __launch_bounds__(256, 2)
void mma_gemm_out(const float* __restrict__ bias, float* __restrict__ Out)
{
    extern __shared__ char smem[];
    gemm_core_h(g_xatth, g_w16[6], bias, Out, nullptr, 2, 1, 1.0f, smem,
                blockIdx.y * 128, blockIdx.x * 128);
}

// ---------------- merged local + global attention (unchanged) ----------------
#define KSTR 72
#define ST_KV 18432
#define L_OK  (3 * ST_KV)                // 55296
#define L_TCL (L_OK + 704)               // 56000
#define LA_SMEM 56320

__device__ void local_attn_body(char* sm, const int* __restrict__ mask)
{
    const uint32_t sbase = smem_u32(sm);
    unsigned char* okarr = (unsigned char*)(sm + L_OK);
    int* tclean = (int*)(sm + L_TCL);

    const int c = blockIdx.x >> 1, h = blockIdx.y, b = blockIdx.z;
    const int rhalf = blockIdx.x & 1;
    const int i0 = rhalf * 128;
    const int tid = threadIdx.x, wid = tid >> 5, lane = tid & 31;
    const int lr = lane >> 2, lc = lane & 3;
    const int l8 = lane & 7, lb = (lane >> 3) & 1, lh = lane >> 4;
    const size_t bh = (size_t)b * HH + h;
    const int s0 = c * WW + i0;
    const int tlo = rhalf * 2;
    const int bandlo = (c - 1) * WW + tlo * 64;

    for (int j = tid; j < 704; j += 256) {
        int ok;
        if (j < 64) ok = 1;
        else {
            int p = bandlo + (j - 64);
            ok = (p >= 0 && p < SS && mask[b * SS + p] == 0) ? 1 : 0;
        }
        okarr[j] = (unsigned char)ok;
    }
    __syncthreads();
    if (tid < 10) {
        const uint32_t* w = (const uint32_t*)(okarr + 64 + tid * 64);
        uint32_t allv = 0xFFFFFFFFu;
#pragma unroll
        for (int q4 = 0; q4 < 16; q4++) allv &= w[q4];
        tclean[tid] = (allv == 0x01010101u) ? 1 : 0;
    }

    uint32_t qa[4][4];
    {
        const __half* qb2 = g_qh + (bh * SS + s0 + wid * 16) * 64;
#pragma unroll
        for (int kk = 0; kk < 4; kk++) {
            qa[kk][0] = *(const uint32_t*)&qb2[(lr)     * 64 + kk * 16 + 2 * lc];
            qa[kk][1] = *(const uint32_t*)&qb2[(lr + 8) * 64 + kk * 16 + 2 * lc];
            qa[kk][2] = *(const uint32_t*)&qb2[(lr)     * 64 + kk * 16 + 8 + 2 * lc];
            qa[kk][3] = *(const uint32_t*)&qb2[(lr + 8) * 64 + kk * 16 + 8 + 2 * lc];
        }
    }

    float o[8][4];
#pragma unroll
    for (int nt = 0; nt < 8; nt++)
#pragma unroll
        for (int e = 0; e < 4; e++) o[nt][e] = 0.f;
    float mrun = -1e30f;
    float lr0 = 0.f, lr1 = 0.f;

    const __half* kbase = g_kh + bh * SS * 64;
    const __half* vbase = g_vh + bh * SS * 64;
    const int wbase = i0 + wid * 16;
    const int irelA = wbase + lr;
    const int irelB = irelA + 8;

    auto issue_tile = [&](int ti) {
        const int pbase = (ti == 0) ? 0 : bandlo + (ti - 1) * 64;
        const uint32_t kdst = sbase + (uint32_t)((ti % 3) * ST_KV);
        const uint32_t vdst = kdst + 9216;
#pragma unroll
        for (int i = 0; i < 4; i++) {
            int li = i * 256 + tid;
            int op = li >> 9;
            int rem = li & 511;
            int row = rem >> 3, ch = rem & 7;
            int p = pbase + row;
            p = (p < 0) ? 0 : ((p >= SS) ? SS - 1 : p);
            const __half* src = (op ? vbase : kbase) + (size_t)p * 64 + ch * 8;
            uint32_t dst = (op ? vdst : kdst) + (uint32_t)(row * (KSTR * 2) + ch * 16);
            CP_ASYNC16(dst, src);
        }
        CP_COMMIT();
    };

    issue_tile(0);
    issue_tile(1);

    for (int ti = 0; ti < 11; ti++) {
        CP_WAIT(1);
        __syncthreads();
        if (ti + 2 < 11) issue_tile(ti + 2);

        if (ti > 0) {
            const int jbase = (tlo + ti - 1) * 64;
            if (jbase + 63 < wbase || jbase > wbase + 15 + 2 * WW) continue;
        }

        const uint32_t kbuf = sbase + (uint32_t)((ti % 3) * ST_KV);
        const uint32_t vbuf = kbuf + 9216;

        float cs[8][4];
#pragma unroll
        for (int nt = 0; nt < 8; nt++)
#pragma unroll
            for (int e = 0; e < 4; e++) cs[nt][e] = 0.f;
#pragma unroll
        for (int kk = 0; kk < 4; kk++) {
#pragma unroll
            for (int g4 = 0; g4 < 4; g4++) {
                uint32_t r0, r1, r2, r3;
                int key = g4 * 16 + l8 + lb * 8;
                int dim = kk * 16 + lh * 8;
                LDSM_X4(r0, r1, r2, r3, kbuf + (uint32_t)(key * (KSTR * 2) + dim * 2));
                MMA_F16(cs[2 * g4],     qa[kk], r0, r2);
                MMA_F16(cs[2 * g4 + 1], qa[kk], r1, r3);
            }
        }

        if (ti > 0) {
            const int jbase = (tlo + ti - 1) * 64;
            const bool interior = (tclean[ti - 1] != 0) &&
                                  (jbase >= wbase + 15) &&
                                  (jbase + 63 <= wbase + 2 * WW);
            if (!interior) {
                const unsigned char* okp = okarr + 64 + (ti - 1) * 64;
#pragma unroll
                for (int nt = 0; nt < 8; nt++) {
                    int jl = nt * 8 + 2 * lc;
                    int j = jbase + jl;
                    bool o0 = okp[jl] != 0, o1 = okp[jl + 1] != 0;
                    if (!(o0 && j     >= irelA && j     <= irelA + 512)) cs[nt][0] = -1e30f;
                    if (!(o1 && j + 1 >= irelA && j + 1 <= irelA + 512)) cs[nt][1] = -1e30f;
                    if (!(o0 && j     >= irelB && j     <= irelB + 512)) cs[nt][2] = -1e30f;
                    if (!(o1 && j + 1 >= irelB && j + 1 <= irelB + 512)) cs[nt][3] = -1e30f;
                }
            }
        }

        float ml = -1e30f;
#pragma unroll
        for (int nt = 0; nt < 8; nt++)
            ml = fmaxf(ml, fmaxf(fmaxf(cs[nt][0], cs[nt][1]), fmaxf(cs[nt][2], cs[nt][3])));
        ml = fmaxf(ml, __shfl_xor_sync(0xffffffffu, ml, 1));
        ml = fmaxf(ml, __shfl_xor_sync(0xffffffffu, ml, 2));
        ml = fmaxf(ml, __shfl_xor_sync(0xffffffffu, ml, 4));
        ml = fmaxf(ml, __shfl_xor_sync(0xffffffffu, ml, 8));
        ml = fmaxf(ml, __shfl_xor_sync(0xffffffffu, ml, 16));
        if (ml > mrun) {
            float corr = fexp2(mrun - ml);
            mrun = ml;
            lr0 *= corr; lr1 *= corr;
#pragma unroll
            for (int nt = 0; nt < 8; nt++) {
                o[nt][0] *= corr; o[nt][1] *= corr;
                o[nt][2] *= corr; o[nt][3] *= corr;
            }
        }
        float ps0 = 0.f, ps1 = 0.f;
        uint32_t pa[4][4];
#pragma unroll
        for (int nt = 0; nt < 8; nt++) {
            float p0 = fexp2(cs[nt][0] - mrun);
            float p1 = fexp2(cs[nt][1] - mrun);
            float p2 = fexp2(cs[nt][2] - mrun);
            float p3 = fexp2(cs[nt][3] - mrun);
            ps0 += p0 + p1; ps1 += p2 + p3;
            pa[nt >> 1][(nt & 1) * 2 + 0] = packh2(p0, p1);
            pa[nt >> 1][(nt & 1) * 2 + 1] = packh2(p2, p3);
        }
        lr0 += ps0; lr1 += ps1;

#pragma unroll
        for (int kk = 0; kk < 4; kk++) {
#pragma unroll
            for (int g4 = 0; g4 < 4; g4++) {
                uint32_t r0, r1, r2, r3;
                int key = kk * 16 + l8 + lb * 8;
                int dim = g4 * 16 + lh * 8;
                LDSM_X4_T(r0, r1, r2, r3, vbuf + (uint32_t)(key * (KSTR * 2) + dim * 2));
                MMA_F16(o[2 * g4],     pa[kk], r0, r1);
                MMA_F16(o[2 * g4 + 1], pa[kk], r2, r3);
            }
        }
    }

#pragma unroll
    for (int e = 0; e < 2; e++) {
        float ll = e ? lr1 : lr0;
        ll += __shfl_xor_sync(0xffffffffu, ll, 1);
        ll += __shfl_xor_sync(0xffffffffu, ll, 2);
        const float inv = 1.f / ll;
        const int srow = s0 + wid * 16 + lr + 8 * e;
        __half* orow = g_xatth + ((size_t)b * SS + srow) * DD + h * 64;
#pragma unroll
        for (int nt = 0; nt < 8; nt++)
            *(uint32_t*)&orow[nt * 8 + 2 * lc] =
                packh2(o[nt][2 * e] * inv, o[nt][2 * e + 1] * inv);
    }
}

__device__ void gattn_body(char* sm, const int* __restrict__ mask)
{
    __half* kgs = (__half*)sm;
    __half* vgs = (__half*)(sm + ST_KV);
    unsigned char* okg = (unsigned char*)(sm + 2 * ST_KV);

    const int split = blockIdx.x - 32, h = blockIdx.y, b = blockIdx.z;
    const int tid = threadIdx.x, wid = tid >> 5, lane = tid & 31;
    const int lr = lane >> 2, lc = lane & 3;
    const int l8 = lane & 7, lb = (lane >> 3) & 1, lh = lane >> 4;
    const size_t bh = (size_t)b * HH + h;
    const int wr = wid & 3, kh = wid >> 2;
    const int p0 = split * 128;

    {
        const __half* kb2 = g_kgh + (bh * SS + p0) * 64;
        const __half* vb2 = g_vgh + (bh * SS + p0) * 64;
        const uint32_t kdst = smem_u32(kgs);
        const uint32_t vdst = smem_u32(vgs);
#pragma unroll
        for (int i = 0; i < 8; i++) {
            int li = i * 256 + tid;
            int op = li >> 10;
            int rem = li & 1023;
            int row = rem >> 3, ch = rem & 7;
            const __half* src = (op ? vb2 : kb2) + (size_t)row * 64 + ch * 8;
            uint32_t dst = (op ? vdst : kdst) + (uint32_t)(row * (KSTR * 2) + ch * 16);
            CP_ASYNC16(dst, src);
        }
        CP_COMMIT();
        if (tid < 128) okg[tid] = (mask[b * SS + p0 + tid] <= 0) ? 1 : 0;
        CP_WAIT(0);
        __syncthreads();
    }

    uint32_t qa[4][4];
    {
        const __half* qb2 = g_qgh + (bh * GG + wr * 16) * 64;
#pragma unroll
        for (int kk = 0; kk < 4; kk++) {
            qa[kk][0] = *(const uint32_t*)&qb2[(lr)     * 64 + kk * 16 + 2 * lc];
            qa[kk][1] = *(const uint32_t*)&qb2[(lr + 8) * 64 + kk * 16 + 2 * lc];
            qa[kk][2] = *(const uint32_t*)&qb2[(lr)     * 64 + kk * 16 + 8 + 2 * lc];
            qa[kk][3] = *(const uint32_t*)&qb2[(lr + 8) * 64 + kk * 16 + 8 + 2 * lc];
        }
    }

    const uint32_t kbuf = smem_u32(kgs) + (uint32_t)(kh * 64 * KSTR * 2);
    const uint32_t vbuf = smem_u32(vgs) + (uint32_t)(kh * 64 * KSTR * 2);

    float cs[8][4];
#pragma unroll
    for (int nt = 0; nt < 8; nt++)
#pragma unroll
        for (int e = 0; e < 4; e++) cs[nt][e] = 0.f;
#pragma unroll
    for (int kk = 0; kk < 4; kk++) {
#pragma unroll
        for (int g4 = 0; g4 < 4; g4++) {
            uint32_t r0, r1, r2, r3;
            int key = g4 * 16 + l8 + lb * 8;
            int dim = kk * 16 + lh * 8;
            LDSM_X4(r0, r1, r2, r3, kbuf + (uint32_t)(key * (KSTR * 2) + dim * 2));
            MMA_F16(cs[2 * g4],     qa[kk], r0, r2);
            MMA_F16(cs[2 * g4 + 1], qa[kk], r1, r3);
        }
    }
#pragma unroll
    for (int nt = 0; nt < 8; nt++) {
        int jl = kh * 64 + nt * 8 + 2 * lc;
        if (!okg[jl])     { cs[nt][0] = -1e30f; cs[nt][2] = -1e30f; }
        if (!okg[jl + 1]) { cs[nt][1] = -1e30f; cs[nt][3] = -1e30f; }
    }
    float ml0 = -1e30f, ml1 = -1e30f;
#pragma unroll
    for (int nt = 0; nt < 8; nt++) {
        ml0 = fmaxf(ml0, fmaxf(cs[nt][0], cs[nt][1]));
        ml1 = fmaxf(ml1, fmaxf(cs[nt][2], cs[nt][3]));
    }
    ml0 = fmaxf(ml0, __shfl_xor_sync(0xffffffffu, ml0, 1));
    ml0 = fmaxf(ml0, __shfl_xor_sync(0xffffffffu, ml0, 2));
    ml1 = fmaxf(ml1, __shfl_xor_sync(0xffffffffu, ml1, 1));
    ml1 = fmaxf(ml1, __shfl_xor_sync(0xffffffffu, ml1, 2));
    float ps0 = 0.f, ps1 = 0.f;
    uint32_t pa[4][4];
#pragma unroll
    for (int nt = 0; nt < 8; nt++) {
        float pp0 = fexp2(cs[nt][0] - ml0);
        float pp1 = fexp2(cs[nt][1] - ml0);
        float pp2 = fexp2(cs[nt][2] - ml1);
        float pp3 = fexp2(cs[nt][3] - ml1);
        ps0 += pp0 + pp1; ps1 += pp2 + pp3;
        pa[nt >> 1][(nt & 1) * 2 + 0] = packh2(pp0, pp1);
        pa[nt >> 1][(nt & 1) * 2 + 1] = packh2(pp2, pp3);
    }
    ps0 += __shfl_xor_sync(0xffffffffu, ps0, 1);
    ps0 += __shfl_xor_sync(0xffffffffu, ps0, 2);
    ps1 += __shfl_xor_sync(0xffffffffu, ps1, 1);
    ps1 += __shfl_xor_sync(0xffffffffu, ps1, 2);

    float o[8][4];
#pragma unroll
    for (int nt = 0; nt < 8; nt++)
#pragma unroll
        for (int e = 0; e < 4; e++) o[nt][e] = 0.f;
#pragma unroll
    for (int kk = 0; kk < 4; kk++) {
#pragma unroll
        for (int g4 = 0; g4 < 4; g4++) {
            uint32_t r0, r1, r2, r3;
            int key = kk * 16 + l8 + lb * 8;
            int dim = g4 * 16 + lh * 8;
            LDSM_X4_T(r0, r1, r2, r3, vbuf + (uint32_t)(key * (KSTR * 2) + dim * 2));
            MMA_F16(o[2 * g4],     pa[kk], r0, r1);
            MMA_F16(o[2 * g4 + 1], pa[kk], r2, r3);
        }
    }

    const int pid = split * 2 + kh;
#pragma unroll
    for (int e = 0; e < 2; e++) {
        const int grow = wr * 16 + lr + 8 * e;
        const size_t idx = (bh * GG + grow) * 64 + pid;
        if (lc == 0) {
            g_pm[idx] = e ? ml1 : ml0;
            g_pl[idx] = e ? ps1 : ps0;
        }
        float* ap = g_pacc + idx * 64;
#pragma unroll
        for (int nt = 0; nt < 8; nt++)
            *(float2*)&ap[nt * 8 + 2 * lc] = make_float2(o[nt][2 * e], o[nt][2 * e + 1]);
    }
}

__global__ __launch_bounds__(256, 2)
void attn_merged(const int* __restrict__ mask)
{
    extern __shared__ char sm[];
    if (blockIdx.x < 32) local_attn_body(sm, mask);
    else                 gattn_body(sm, mask);
}

__global__ void gattn_combine_kernel(void)
{
    const int rid = blockIdx.x * blockDim.x + threadIdx.x;
    if (rid >= BB * HH * GG) return;
    float M = -1e30f;
    for (int p = 0; p < 64; p++) M = fmaxf(M, g_pm[(size_t)rid * 64 + p]);
    float L = 0.f;
    float acc[64];
#pragma unroll
    for (int d = 0; d < 64; d++) acc[d] = 0.f;
    for (int p = 0; p < 64; p++) {
        const float w = fexp2(g_pm[(size_t)rid * 64 + p] - M);
        L += g_pl[(size_t)rid * 64 + p] * w;
        const float* ap = g_pacc + ((size_t)rid * 64 + p) * 64;
#pragma unroll
        for (int d = 0; d < 64; d += 4) {
            float4 a4 = *(const float4*)(ap + d);
            acc[d]   += w * a4.x;
            acc[d+1] += w * a4.y;
            acc[d+2] += w * a4.z;
            acc[d+3] += w * a4.w;
        }
    }
    const float inv = 1.f / L;
    const int bh = rid >> 6, g = rid & 63;
    const int b = bh / HH, h = bh % HH;
    __half* orow = g_xatth + ((size_t)b * SS + g) * DD + h * 64;
#pragma unroll
    for (int d = 0; d < 64; d += 2)
        *(uint32_t*)&orow[d] = packh2(acc[d] * inv, acc[d + 1] * inv);
}

// ---------------- launcher ----------------
extern "C" void kernel_launch(void* const* d_in, const int* in_sizes, int n_in,
                              void* d_out, int out_size)
{
    (void)in_sizes; (void)n_in; (void)out_size;
    const float* query = (const float*)d_in[0];
    const int*   mask  = (const int*)d_in[1];
    const float* Wq  = (const float*)d_in[2];
    const float* bq  = (const float*)d_in[3];
    const float* Wk  = (const float*)d_in[4];
    const float* bk  = (const float*)d_in[5];
    const float* Wv  = (const float*)d_in[6];
    const float* bv  = (const float*)d_in[7];
    const float* Wqg = (const float*)d_in[8];
    const float* bqg = (const float*)d_in[9];
    const float* Wkg = (const float*)d_in[10];
    const float* bkg = (const float*)d_in[11];
    const float* Wvg = (const float*)d_in[12];
    const float* bvg = (const float*)d_in[13];
    const float* Wo  = (const float*)d_in[14];
    const float* bo  = (const float*)d_in[15];
    float* out = (float*)d_out;

    __half *qb, *kb, *vb, *kgb, *vgb, *qgb;
    cudaGetSymbolAddress((void**)&qb,  g_qh);
    cudaGetSymbolAddress((void**)&kb,  g_kh);
    cudaGetSymbolAddress((void**)&vb,  g_vh);
    cudaGetSymbolAddress((void**)&kgb, g_kgh);
    cudaGetSymbolAddress((void**)&vgb, g_vgh);
    cudaGetSymbolAddress((void**)&qgb, g_qgh);

    cudaFuncSetAttribute(mma_gemm6,    cudaFuncAttributeMaxDynamicSharedMemorySize, SMT);
    cudaFuncSetAttribute(mma_gemm_out, cudaFuncAttributeMaxDynamicSharedMemorySize, SMT);
    cudaFuncSetAttribute(attn_merged,  cudaFuncAttributeMaxDynamicSharedMemorySize, LA_SMEM);

    // launch 0: weight fp32->fp16 converts
    W7 w7;
    w7.w[0] = Wq; w7.w[1] = Wk; w7.w[2] = Wv; w7.w[3] = Wkg;
    w7.w[4] = Wvg; w7.w[5] = Wqg; w7.w[6] = Wo;
    k_cvt_w<<<dim3((DD * DD / 4 + 255) / 256, 7), 256>>>(w7);

    // launches 1,2: x fp32->fp16 convert split in two (puts gemm6 at profile idx 3)
    const int ntot4 = BB * SS * DD / 4;          // 1572864 float4s
    const int half4 = ntot4 / 2;
    k_cvt_x<<<(half4 + 255) / 256, 256>>>(query, 0);
    k_cvt_x<<<(half4 + 255) / 256, 256>>>(query, half4);

    // launch 3: 6 batched GEMMs (4-stage pipeline) — PROFILE SLOT
    Gemm6 p6;
    p6.bias[0] = bq;  p6.out[0] = qb;  p6.scale[0] = QSCALE;
    p6.bias[1] = bk;  p6.out[1] = kb;  p6.scale[1] = 1.0f;
    p6.bias[2] = bv;  p6.out[2] = vb;  p6.scale[2] = 1.0f;
    p6.bias[3] = bkg; p6.out[3] = kgb; p6.scale[3] = 1.0f;
    p6.bias[4] = bvg; p6.out[4] = vgb; p6.scale[4] = 1.0f;
    p6.bias[5] = bqg; p6.out[5] = qgb; p6.scale[5] = QSCALE;
    mma_gemm6<<<dim3(6, 64, 6), 256, SMT>>>(p6);

    // launch 4: merged local + global attention
    attn_merged<<<dim3(64, HH, BB), 256, LA_SMEM>>>(mask);

    // launch 5: combine global partials
    gattn_combine_kernel<<<(BB * HH * GG + 255) / 256, 256>>>();

    // launch 6: final GEMM
    mma_gemm_out<<<dim3(6, 64), 256, SMT>>>(bo, out);
}

// round 13
// speedup vs baseline: 1.0092x; 1.0092x over previous
#include <cuda_runtime.h>
#include <cuda_fp16.h>
#include <math.h>
#include <cstdint>

// Problem constants
#define BB 2
#define SS 4096
#define DD 768
#define HH 12
#define GG 64
#define HD 64
#define WW 256
#define NCC 16
#define NHEADS_S ((size_t)BB * HH * SS * HD)   // 6291456
#define QSCALE (0.125f * 1.4426950408889634f)  // fold log2e: softmax in exp2 domain

// ---------------- scratch (static device globals; no allocation) ----------------
__device__ __half g_xh  [(size_t)BB * SS * DD];      // x fp16, SAME (S,B,D) order as input
__device__ __half g_w16 [7][(size_t)DD * DD];        // W fp16, un-transposed (k,n)
__device__ __half g_qh  [NHEADS_S];                  // [b][h][s][hd], scaled by QSCALE
__device__ __half g_kh  [NHEADS_S];
__device__ __half g_vh  [NHEADS_S];
__device__ __half g_kgh [NHEADS_S];
__device__ __half g_vgh [NHEADS_S];
__device__ __half g_qgh [(size_t)BB * HH * GG * HD];
__device__ __half g_xatth[(size_t)BB * SS * DD];     // attention out, row-major (b,s,d)
__device__ float g_pm   [(size_t)BB * HH * GG * 64];
__device__ float g_pl   [(size_t)BB * HH * GG * 64];
__device__ float g_pacc [(size_t)BB * HH * GG * 64 * HD];

// ---------------- helpers ----------------
__device__ __forceinline__ uint32_t smem_u32(const void* p) {
    uint32_t a;
    asm("{ .reg .u64 t; cvta.to.shared.u64 t, %1; cvt.u32.u64 %0, t; }" : "=r"(a) : "l"(p));
    return a;
}
__device__ __forceinline__ uint32_t packh2(float a, float b) {
    __half2 h = __floats2half2_rn(a, b);
    return *reinterpret_cast<uint32_t*>(&h);
}
// 2^x on the FMA pipe: magic round-to-nearest, degree-4 poly on [-0.5, 0.5]
__device__ __forceinline__ float fexp2(float x) {
    float t = fmaxf(x, -125.0f);
    float r = t + 12582912.0f;
    float fi = r - 12582912.0f;
    float f = t - fi;
    int n = __float_as_int(r) - 0x4B400000;
    float p = 9.61812911e-3f;
    p = fmaf(p, f, 5.55041087e-2f);
    p = fmaf(p, f, 2.40226507e-1f);
    p = fmaf(p, f, 6.93147180e-1f);
    p = fmaf(p, f, 1.0f);
    return __int_as_float((n + 127) << 23) * p;
}
#define CP_ASYNC16(saddr, gptr) \
    asm volatile("cp.async.cg.shared.global [%0], [%1], 16;" :: "r"(saddr), "l"(gptr))
#define CP_COMMIT() asm volatile("cp.async.commit_group;" ::: "memory")
#define CP_WAIT(N)  asm volatile("cp.async.wait_group %0;" :: "n"(N) : "memory")

#define MMA_F16(d, a, b0v, b1v) \
    asm volatile( \
        "mma.sync.aligned.m16n8k16.row.col.f32.f16.f16.f32 " \
        "{%0,%1,%2,%3}, {%4,%5,%6,%7}, {%8,%9}, {%0,%1,%2,%3};" \
        : "+f"((d)[0]), "+f"((d)[1]), "+f"((d)[2]), "+f"((d)[3]) \
        : "r"((a)[0]), "r"((a)[1]), "r"((a)[2]), "r"((a)[3]), \
          "r"(b0v), "r"(b1v))

#define LDSM_X4(r0, r1, r2, r3, addr) \
    asm volatile("ldmatrix.sync.aligned.m8n8.x4.shared.b16 {%0,%1,%2,%3}, [%4];" \
                 : "=r"(r0), "=r"(r1), "=r"(r2), "=r"(r3) : "r"(addr))
#define LDSM_X4_T(r0, r1, r2, r3, addr) \
    asm volatile("ldmatrix.sync.aligned.m8n8.x4.trans.shared.b16 {%0,%1,%2,%3}, [%4];" \
                 : "=r"(r0), "=r"(r1), "=r"(r2), "=r"(r3) : "r"(addr))

// ---------------- elementwise fp32 -> fp16 converts (no transposes) ----------------
__global__ void k_cvt_x(const float* __restrict__ src) {
    size_t t = ((size_t)blockIdx.x * blockDim.x + threadIdx.x) * 4;
    if (t >= (size_t)BB * SS * DD) return;
    float4 v = *(const float4*)(src + t);
    *(uint32_t*)&g_xh[t]     = packh2(v.x, v.y);
    *(uint32_t*)&g_xh[t + 2] = packh2(v.z, v.w);
}
struct W7 { const float* w[7]; };
__global__ void k_cvt_w(W7 p) {
    const float* src = p.w[blockIdx.y];
    __half* dst = g_w16[blockIdx.y];
    size_t t = ((size_t)blockIdx.x * blockDim.x + threadIdx.x) * 4;
    if (t >= (size_t)DD * DD) return;
    float4 v = *(const float4*)(src + t);
    *(uint32_t*)&dst[t]     = packh2(v.x, v.y);
    *(uint32_t*)&dst[t + 2] = packh2(v.z, v.w);
}

// ---------------- fp16 mma.sync GEMM core (128x128, 256 thr, trans-B, 4-stage) ----------------
// A: 128 rows x 32 halves/chunk, stride 80B. B: W direct (k,n): 32 k-rows x 256B,
// stride 272B. 4-stage cp.async, CP_WAIT(2), ONE barrier per chunk (post-barrier
// issue targets stage (c-1)%4 whose reads completed before the barrier).
#define OPA 10240                 // A bytes per stage (128*80)
#define BSTR 272                  // B row stride bytes
#define STG 19456                 // stage bytes (10240 + 8704, padded)
#define NSTAGE 4
#define SMT (NSTAGE * STG)        // 77824 (dynamic)

__device__ __forceinline__ void gemm_core_h(
    const __half* __restrict__ X, const __half* __restrict__ Wm,
    const float* __restrict__ bias, float* __restrict__ OutF, __half* __restrict__ OutH,
    int in_mode, int out_mode, float scale, char* smem, int m0, int n0)
{
    const uint32_t sbase = smem_u32(smem);
    const int tid = threadIdx.x;
    const int wid = tid >> 5, lane = tid & 31;
    const int wm = (wid >> 2) * 64;
    const int wn = (wid & 3) * 32;
    const int lr = lane >> 2;
    const int lc = lane & 3;
    const int l16 = lane & 15, lh = lane >> 4;
    const int l8 = lane & 7, lb = (lane >> 3) & 1;

    const __half* arow[2];
    const __half* brow[2];
    uint32_t dstoA[2], dstoB[2];
#pragma unroll
    for (int i = 0; i < 2; i++) {
        int li = i * 256 + tid;
        {   // A
            int row = li >> 2, col4 = li & 3;
            int gr = m0 + row;
            int grow;
            if (in_mode == 0)      grow = (gr & 4095) * 2 + (gr >> 12);
            else if (in_mode == 1) grow = (gr & 63) * 2 + (gr >> 6);
            else                   grow = gr;
            arow[i]  = X + (size_t)grow * 768 + col4 * 8;
            dstoA[i] = (uint32_t)(row * 80 + col4 * 16);
        }
        {   // B: row = k (0..31), col16 = n/8 (0..15)
            int row = li >> 4, col16 = li & 15;
            brow[i]  = Wm + (size_t)row * 768 + n0 + col16 * 8;
            dstoB[i] = (uint32_t)(OPA + row * BSTR + col16 * 16);
        }
    }

    float acc[4][4][4];
#pragma unroll
    for (int mt = 0; mt < 4; mt++)
#pragma unroll
        for (int nt = 0; nt < 4; nt++)
#pragma unroll
            for (int e = 0; e < 4; e++) acc[mt][nt][e] = 0.f;

    auto issue = [&](int cc) {
        const int kn = cc * 32;
        const uint32_t st = sbase + (uint32_t)(cc % NSTAGE) * STG;
#pragma unroll
        for (int i = 0; i < 2; i++) {
            CP_ASYNC16(st + dstoA[i], arow[i] + kn);
            CP_ASYNC16(st + dstoB[i], brow[i] + (size_t)kn * 768);
        }
        CP_COMMIT();
    };

    issue(0);
    issue(1);
    issue(2);

    for (int c = 0; c < 24; c++) {
        CP_WAIT(2);
        __syncthreads();
        if (c + 3 < 24) issue(c + 3);     // stage (c+3)%4 == (c-1)%4: safe post-barrier

        const uint32_t abase = sbase + (uint32_t)(c % NSTAGE) * STG;
        const uint32_t bbase = abase + OPA;

#pragma unroll
        for (int ks = 0; ks < 2; ks++) {
            const uint32_t koff = (uint32_t)(ks * 16 + lh * 8) * 2;
            uint32_t af[4][4];
#pragma unroll
            for (int mt = 0; mt < 4; mt++)
                LDSM_X4(af[mt][0], af[mt][1], af[mt][2], af[mt][3],
                        abase + (uint32_t)(wm + mt * 16 + l16) * 80 + koff);
            uint32_t bf[2][4];
#pragma unroll
            for (int g2 = 0; g2 < 2; g2++) {
                int krow = ks * 16 + l8 + lb * 8;
                int ncol = wn + g2 * 16 + lh * 8;
                LDSM_X4_T(bf[g2][0], bf[g2][1], bf[g2][2], bf[g2][3],
                          bbase + (uint32_t)(krow * BSTR + ncol * 2));
            }
#pragma unroll
            for (int mt = 0; mt < 4; mt++)
#pragma unroll
                for (int g2 = 0; g2 < 2; g2++) {
                    MMA_F16(acc[mt][2 * g2],     af[mt], bf[g2][0], bf[g2][1]);
                    MMA_F16(acc[mt][2 * g2 + 1], af[mt], bf[g2][2], bf[g2][3]);
                }
        }
    }

#pragma unroll
    for (int mt = 0; mt < 4; mt++) {
#pragma unroll
        for (int half = 0; half < 2; half++) {
            const int rr = m0 + wm + mt * 16 + lr + half * 8;
#pragma unroll
            for (int nt = 0; nt < 4; nt++) {
                const int nn = n0 + wn + nt * 8 + lc * 2;
                float v0 = (acc[mt][nt][half * 2 + 0] + bias[nn])     * scale;
                float v1 = (acc[mt][nt][half * 2 + 1] + bias[nn + 1]) * scale;
                if (out_mode == 1) {
                    int bb = rr >> 12, ss = rr & 4095;
                    *(float2*)(OutF + ((size_t)ss * BB + bb) * DD + nn) = make_float2(v0, v1);
                } else if (out_mode == 0) {
                    int bb = rr >> 12, ss = rr & 4095;
                    int h = nn >> 6, hd0 = nn & 63;
                    *(uint32_t*)(OutH + ((((size_t)bb * HH + h) * SS + ss) * 64 + hd0)) = packh2(v0, v1);
                } else {
                    int bb = rr >> 6, gg2 = rr & 63;
                    int h = nn >> 6, hd0 = nn & 63;
                    *(uint32_t*)(OutH + ((((size_t)bb * HH + h) * GG + gg2) * 64 + hd0)) = packh2(v0, v1);
                }
            }
        }
    }
}

struct Gemm6 { const float* bias[6]; __half* out[6]; float scale[6]; };
__global__ __launch_bounds__(256, 2)
void mma_gemm6(Gemm6 p)
{
    extern __shared__ char smem[];
    const int z = blockIdx.z;
    if (z == 5) {
        if (blockIdx.y != 0) return;
        gemm_core_h(g_xh, g_w16[5], p.bias[5], nullptr, p.out[5], 1, 2, p.scale[5], smem,
                    0, blockIdx.x * 128);
    } else {
        gemm_core_h(g_xh, g_w16[z], p.bias[z], nullptr, p.out[z], 0, 0, p.scale[z], smem,
                    blockIdx.y * 128, blockIdx.x * 128);
    }
}
__global__ __launch_bounds__(256, 2)
void mma_gemm_out(const float* __restrict__ bias, float* __restrict__ Out)
{
    extern __shared__ char smem[];
    gemm_core_h(g_xatth, g_w16[6], bias, Out, nullptr, 2, 1, 1.0f, smem,
                blockIdx.y * 128, blockIdx.x * 128);
}

// ---------------- merged local + global attention (unchanged) ----------------
#define KSTR 72
#define ST_KV 18432
#define L_OK  (3 * ST_KV)                // 55296
#define L_TCL (L_OK + 704)               // 56000
#define LA_SMEM 56320

__device__ void local_attn_body(char* sm, const int* __restrict__ mask)
{
    const uint32_t sbase = smem_u32(sm);
    unsigned char* okarr = (unsigned char*)(sm + L_OK);
    int* tclean = (int*)(sm + L_TCL);

    const int c = blockIdx.x >> 1, h = blockIdx.y, b = blockIdx.z;
    const int rhalf = blockIdx.x & 1;
    const int i0 = rhalf * 128;
    const int tid = threadIdx.x, wid = tid >> 5, lane = tid & 31;
    const int lr = lane >> 2, lc = lane & 3;
    const int l8 = lane & 7, lb = (lane >> 3) & 1, lh = lane >> 4;
    const size_t bh = (size_t)b * HH + h;
    const int s0 = c * WW + i0;
    const int tlo = rhalf * 2;
    const int bandlo = (c - 1) * WW + tlo * 64;

    for (int j = tid; j < 704; j += 256) {
        int ok;
        if (j < 64) ok = 1;
        else {
            int p = bandlo + (j - 64);
            ok = (p >= 0 && p < SS && mask[b * SS + p] == 0) ? 1 : 0;
        }
        okarr[j] = (unsigned char)ok;
    }
    __syncthreads();
    if (tid < 10) {
        const uint32_t* w = (const uint32_t*)(okarr + 64 + tid * 64);
        uint32_t allv = 0xFFFFFFFFu;
#pragma unroll
        for (int q4 = 0; q4 < 16; q4++) allv &= w[q4];
        tclean[tid] = (allv == 0x01010101u) ? 1 : 0;
    }

    uint32_t qa[4][4];
    {
        const __half* qb2 = g_qh + (bh * SS + s0 + wid * 16) * 64;
#pragma unroll
        for (int kk = 0; kk < 4; kk++) {
            qa[kk][0] = *(const uint32_t*)&qb2[(lr)     * 64 + kk * 16 + 2 * lc];
            qa[kk][1] = *(const uint32_t*)&qb2[(lr + 8) * 64 + kk * 16 + 2 * lc];
            qa[kk][2] = *(const uint32_t*)&qb2[(lr)     * 64 + kk * 16 + 8 + 2 * lc];
            qa[kk][3] = *(const uint32_t*)&qb2[(lr + 8) * 64 + kk * 16 + 8 + 2 * lc];
        }
    }

    float o[8][4];
#pragma unroll
    for (int nt = 0; nt < 8; nt++)
#pragma unroll
        for (int e = 0; e < 4; e++) o[nt][e] = 0.f;
    float mrun = -1e30f;
    float lr0 = 0.f, lr1 = 0.f;

    const __half* kbase = g_kh + bh * SS * 64;
    const __half* vbase = g_vh + bh * SS * 64;
    const int wbase = i0 + wid * 16;
    const int irelA = wbase + lr;
    const int irelB = irelA + 8;

    auto issue_tile = [&](int ti) {
        const int pbase = (ti == 0) ? 0 : bandlo + (ti - 1) * 64;
        const uint32_t kdst = sbase + (uint32_t)((ti % 3) * ST_KV);
        const uint32_t vdst = kdst + 9216;
#pragma unroll
        for (int i = 0; i < 4; i++) {
            int li = i * 256 + tid;
            int op = li >> 9;
            int rem = li & 511;
            int row = rem >> 3, ch = rem & 7;
            int p = pbase + row;
            p = (p < 0) ? 0 : ((p >= SS) ? SS - 1 : p);
            const __half* src = (op ? vbase : kbase) + (size_t)p * 64 + ch * 8;
            uint32_t dst = (op ? vdst : kdst) + (uint32_t)(row * (KSTR * 2) + ch * 16);
            CP_ASYNC16(dst, src);
        }
        CP_COMMIT();
    };

    issue_tile(0);
    issue_tile(1);

    for (int ti = 0; ti < 11; ti++) {
        CP_WAIT(1);
        __syncthreads();
        if (ti + 2 < 11) issue_tile(ti + 2);

        if (ti > 0) {
            const int jbase = (tlo + ti - 1) * 64;
            if (jbase + 63 < wbase || jbase > wbase + 15 + 2 * WW) continue;
        }

        const uint32_t kbuf = sbase + (uint32_t)((ti % 3) * ST_KV);
        const uint32_t vbuf = kbuf + 9216;

        float cs[8][4];
#pragma unroll
        for (int nt = 0; nt < 8; nt++)
#pragma unroll
            for (int e = 0; e < 4; e++) cs[nt][e] = 0.f;
#pragma unroll
        for (int kk = 0; kk < 4; kk++) {
#pragma unroll
            for (int g4 = 0; g4 < 4; g4++) {
                uint32_t r0, r1, r2, r3;
                int key = g4 * 16 + l8 + lb * 8;
                int dim = kk * 16 + lh * 8;
                LDSM_X4(r0, r1, r2, r3, kbuf + (uint32_t)(key * (KSTR * 2) + dim * 2));
                MMA_F16(cs[2 * g4],     qa[kk], r0, r2);
                MMA_F16(cs[2 * g4 + 1], qa[kk], r1, r3);
            }
        }

        if (ti > 0) {
            const int jbase = (tlo + ti - 1) * 64;
            const bool interior = (tclean[ti - 1] != 0) &&
                                  (jbase >= wbase + 15) &&
                                  (jbase + 63 <= wbase + 2 * WW);
            if (!interior) {
                const unsigned char* okp = okarr + 64 + (ti - 1) * 64;
#pragma unroll
                for (int nt = 0; nt < 8; nt++) {
                    int jl = nt * 8 + 2 * lc;
                    int j = jbase + jl;
                    bool o0 = okp[jl] != 0, o1 = okp[jl + 1] != 0;
                    if (!(o0 && j     >= irelA && j     <= irelA + 512)) cs[nt][0] = -1e30f;
                    if (!(o1 && j + 1 >= irelA && j + 1 <= irelA + 512)) cs[nt][1] = -1e30f;
                    if (!(o0 && j     >= irelB && j     <= irelB + 512)) cs[nt][2] = -1e30f;
                    if (!(o1 && j + 1 >= irelB && j + 1 <= irelB + 512)) cs[nt][3] = -1e30f;
                }
            }
        }

        float ml = -1e30f;
#pragma unroll
        for (int nt = 0; nt < 8; nt++)
            ml = fmaxf(ml, fmaxf(fmaxf(cs[nt][0], cs[nt][1]), fmaxf(cs[nt][2], cs[nt][3])));
        ml = fmaxf(ml, __shfl_xor_sync(0xffffffffu, ml, 1));
        ml = fmaxf(ml, __shfl_xor_sync(0xffffffffu, ml, 2));
        ml = fmaxf(ml, __shfl_xor_sync(0xffffffffu, ml, 4));
        ml = fmaxf(ml, __shfl_xor_sync(0xffffffffu, ml, 8));
        ml = fmaxf(ml, __shfl_xor_sync(0xffffffffu, ml, 16));
        if (ml > mrun) {
            float corr = fexp2(mrun - ml);
            mrun = ml;
            lr0 *= corr; lr1 *= corr;
#pragma unroll
            for (int nt = 0; nt < 8; nt++) {
                o[nt][0] *= corr; o[nt][1] *= corr;
                o[nt][2] *= corr; o[nt][3] *= corr;
            }
        }
        float ps0 = 0.f, ps1 = 0.f;
        uint32_t pa[4][4];
#pragma unroll
        for (int nt = 0; nt < 8; nt++) {
            float p0 = fexp2(cs[nt][0] - mrun);
            float p1 = fexp2(cs[nt][1] - mrun);
            float p2 = fexp2(cs[nt][2] - mrun);
            float p3 = fexp2(cs[nt][3] - mrun);
            ps0 += p0 + p1; ps1 += p2 + p3;
            pa[nt >> 1][(nt & 1) * 2 + 0] = packh2(p0, p1);
            pa[nt >> 1][(nt & 1) * 2 + 1] = packh2(p2, p3);
        }
        lr0 += ps0; lr1 += ps1;

#pragma unroll
        for (int kk = 0; kk < 4; kk++) {
#pragma unroll
            for (int g4 = 0; g4 < 4; g4++) {
                uint32_t r0, r1, r2, r3;
                int key = kk * 16 + l8 + lb * 8;
                int dim = g4 * 16 + lh * 8;
                LDSM_X4_T(r0, r1, r2, r3, vbuf + (uint32_t)(key * (KSTR * 2) + dim * 2));
                MMA_F16(o[2 * g4],     pa[kk], r0, r1);
                MMA_F16(o[2 * g4 + 1], pa[kk], r2, r3);
            }
        }
    }

#pragma unroll
    for (int e = 0; e < 2; e++) {
        float ll = e ? lr1 : lr0;
        ll += __shfl_xor_sync(0xffffffffu, ll, 1);
        ll += __shfl_xor_sync(0xffffffffu, ll, 2);
        const float inv = 1.f / ll;
        const int srow = s0 + wid * 16 + lr + 8 * e;
        __half* orow = g_xatth + ((size_t)b * SS + srow) * DD + h * 64;
#pragma unroll
        for (int nt = 0; nt < 8; nt++)
            *(uint32_t*)&orow[nt * 8 + 2 * lc] =
                packh2(o[nt][2 * e] * inv, o[nt][2 * e + 1] * inv);
    }
}

__device__ void gattn_body(char* sm, const int* __restrict__ mask)
{
    __half* kgs = (__half*)sm;
    __half* vgs = (__half*)(sm + ST_KV);
    unsigned char* okg = (unsigned char*)(sm + 2 * ST_KV);

    const int split = blockIdx.x - 32, h = blockIdx.y, b = blockIdx.z;
    const int tid = threadIdx.x, wid = tid >> 5, lane = tid & 31;
    const int lr = lane >> 2, lc = lane & 3;
    const int l8 = lane & 7, lb = (lane >> 3) & 1, lh = lane >> 4;
    const size_t bh = (size_t)b * HH + h;
    const int wr = wid & 3, kh = wid >> 2;
    const int p0 = split * 128;

    {
        const __half* kb2 = g_kgh + (bh * SS + p0) * 64;
        const __half* vb2 = g_vgh + (bh * SS + p0) * 64;
        const uint32_t kdst = smem_u32(kgs);
        const uint32_t vdst = smem_u32(vgs);
#pragma unroll
        for (int i = 0; i < 8; i++) {
            int li = i * 256 + tid;
            int op = li >> 10;
            int rem = li & 1023;
            int row = rem >> 3, ch = rem & 7;
            const __half* src = (op ? vb2 : kb2) + (size_t)row * 64 + ch * 8;
            uint32_t dst = (op ? vdst : kdst) + (uint32_t)(row * (KSTR * 2) + ch * 16);
            CP_ASYNC16(dst, src);
        }
        CP_COMMIT();
        if (tid < 128) okg[tid] = (mask[b * SS + p0 + tid] <= 0) ? 1 : 0;
        CP_WAIT(0);
        __syncthreads();
    }

    uint32_t qa[4][4];
    {
        const __half* qb2 = g_qgh + (bh * GG + wr * 16) * 64;
#pragma unroll
        for (int kk = 0; kk < 4; kk++) {
            qa[kk][0] = *(const uint32_t*)&qb2[(lr)     * 64 + kk * 16 + 2 * lc];
            qa[kk][1] = *(const uint32_t*)&qb2[(lr + 8) * 64 + kk * 16 + 2 * lc];
            qa[kk][2] = *(const uint32_t*)&qb2[(lr)     * 64 + kk * 16 + 8 + 2 * lc];
            qa[kk][3] = *(const uint32_t*)&qb2[(lr + 8) * 64 + kk * 16 + 8 + 2 * lc];
        }
    }

    const uint32_t kbuf = smem_u32(kgs) + (uint32_t)(kh * 64 * KSTR * 2);
    const uint32_t vbuf = smem_u32(vgs) + (uint32_t)(kh * 64 * KSTR * 2);

    float cs[8][4];
#pragma unroll
    for (int nt = 0; nt < 8; nt++)
#pragma unroll
        for (int e = 0; e < 4; e++) cs[nt][e] = 0.f;
#pragma unroll
    for (int kk = 0; kk < 4; kk++) {
#pragma unroll
        for (int g4 = 0; g4 < 4; g4++) {
            uint32_t r0, r1, r2, r3;
            int key = g4 * 16 + l8 + lb * 8;
            int dim = kk * 16 + lh * 8;
            LDSM_X4(r0, r1, r2, r3, kbuf + (uint32_t)(key * (KSTR * 2) + dim * 2));
            MMA_F16(cs[2 * g4],     qa[kk], r0, r2);
            MMA_F16(cs[2 * g4 + 1], qa[kk], r1, r3);
        }
    }
#pragma unroll
    for (int nt = 0; nt < 8; nt++) {
        int jl = kh * 64 + nt * 8 + 2 * lc;
        if (!okg[jl])     { cs[nt][0] = -1e30f; cs[nt][2] = -1e30f; }
        if (!okg[jl + 1]) { cs[nt][1] = -1e30f; cs[nt][3] = -1e30f; }
    }
    float ml0 = -1e30f, ml1 = -1e30f;
#pragma unroll
    for (int nt = 0; nt < 8; nt++) {
        ml0 = fmaxf(ml0, fmaxf(cs[nt][0], cs[nt][1]));
        ml1 = fmaxf(ml1, fmaxf(cs[nt][2], cs[nt][3]));
    }
    ml0 = fmaxf(ml0, __shfl_xor_sync(0xffffffffu, ml0, 1));
    ml0 = fmaxf(ml0, __shfl_xor_sync(0xffffffffu, ml0, 2));
    ml1 = fmaxf(ml1, __shfl_xor_sync(0xffffffffu, ml1, 1));
    ml1 = fmaxf(ml1, __shfl_xor_sync(0xffffffffu, ml1, 2));
    float ps0 = 0.f, ps1 = 0.f;
    uint32_t pa[4][4];
#pragma unroll
    for (int nt = 0; nt < 8; nt++) {
        float pp0 = fexp2(cs[nt][0] - ml0);
        float pp1 = fexp2(cs[nt][1] - ml0);
        float pp2 = fexp2(cs[nt][2] - ml1);
        float pp3 = fexp2(cs[nt][3] - ml1);
        ps0 += pp0 + pp1; ps1 += pp2 + pp3;
        pa[nt >> 1][(nt & 1) * 2 + 0] = packh2(pp0, pp1);
        pa[nt >> 1][(nt & 1) * 2 + 1] = packh2(pp2, pp3);
    }
    ps0 += __shfl_xor_sync(0xffffffffu, ps0, 1);
    ps0 += __shfl_xor_sync(0xffffffffu, ps0, 2);
    ps1 += __shfl_xor_sync(0xffffffffu, ps1, 1);
    ps1 += __shfl_xor_sync(0xffffffffu, ps1, 2);

    float o[8][4];
#pragma unroll
    for (int nt = 0; nt < 8; nt++)
#pragma unroll
        for (int e = 0; e < 4; e++) o[nt][e] = 0.f;
#pragma unroll
    for (int kk = 0; kk < 4; kk++) {
#pragma unroll
        for (int g4 = 0; g4 < 4; g4++) {
            uint32_t r0, r1, r2, r3;
            int key = kk * 16 + l8 + lb * 8;
            int dim = g4 * 16 + lh * 8;
            LDSM_X4_T(r0, r1, r2, r3, vbuf + (uint32_t)(key * (KSTR * 2) + dim * 2));
            MMA_F16(o[2 * g4],     pa[kk], r0, r1);
            MMA_F16(o[2 * g4 + 1], pa[kk], r2, r3);
        }
    }

    const int pid = split * 2 + kh;
#pragma unroll
    for (int e = 0; e < 2; e++) {
        const int grow = wr * 16 + lr + 8 * e;
        const size_t idx = (bh * GG + grow) * 64 + pid;
        if (lc == 0) {
            g_pm[idx] = e ? ml1 : ml0;
            g_pl[idx] = e ? ps1 : ps0;
        }
        float* ap = g_pacc + idx * 64;
#pragma unroll
        for (int nt = 0; nt < 8; nt++)
            *(float2*)&ap[nt * 8 + 2 * lc] = make_float2(o[nt][2 * e], o[nt][2 * e + 1]);
    }
}

__global__ __launch_bounds__(256, 2)
void attn_merged(const int* __restrict__ mask)
{
    extern __shared__ char sm[];
    if (blockIdx.x < 32) local_attn_body(sm, mask);
    else                 gattn_body(sm, mask);
}

__global__ void gattn_combine_kernel(void)
{
    const int rid = blockIdx.x * blockDim.x + threadIdx.x;
    if (rid >= BB * HH * GG) return;
    float M = -1e30f;
    for (int p = 0; p < 64; p++) M = fmaxf(M, g_pm[(size_t)rid * 64 + p]);
    float L = 0.f;
    float acc[64];
#pragma unroll
    for (int d = 0; d < 64; d++) acc[d] = 0.f;
    for (int p = 0; p < 64; p++) {
        const float w = fexp2(g_pm[(size_t)rid * 64 + p] - M);
        L += g_pl[(size_t)rid * 64 + p] * w;
        const float* ap = g_pacc + ((size_t)rid * 64 + p) * 64;
#pragma unroll
        for (int d = 0; d < 64; d += 4) {
            float4 a4 = *(const float4*)(ap + d);
            acc[d]   += w * a4.x;
            acc[d+1] += w * a4.y;
            acc[d+2] += w * a4.z;
            acc[d+3] += w * a4.w;
        }
    }
    const float inv = 1.f / L;
    const int bh = rid >> 6, g = rid & 63;
    const int b = bh / HH, h = bh % HH;
    __half* orow = g_xatth + ((size_t)b * SS + g) * DD + h * 64;
#pragma unroll
    for (int d = 0; d < 64; d += 2)
        *(uint32_t*)&orow[d] = packh2(acc[d] * inv, acc[d + 1] * inv);
}

// ---------------- launcher ----------------
extern "C" void kernel_launch(void* const* d_in, const int* in_sizes, int n_in,
                              void* d_out, int out_size)
{
    (void)in_sizes; (void)n_in; (void)out_size;
    const float* query = (const float*)d_in[0];
    const int*   mask  = (const int*)d_in[1];
    const float* Wq  = (const float*)d_in[2];
    const float* bq  = (const float*)d_in[3];
    const float* Wk  = (const float*)d_in[4];
    const float* bk  = (const float*)d_in[5];
    const float* Wv  = (const float*)d_in[6];
    const float* bv  = (const float*)d_in[7];
    const float* Wqg = (const float*)d_in[8];
    const float* bqg = (const float*)d_in[9];
    const float* Wkg = (const float*)d_in[10];
    const float* bkg = (const float*)d_in[11];
    const float* Wvg = (const float*)d_in[12];
    const float* bvg = (const float*)d_in[13];
    const float* Wo  = (const float*)d_in[14];
    const float* bo  = (const float*)d_in[15];
    float* out = (float*)d_out;

    __half *qb, *kb, *vb, *kgb, *vgb, *qgb;
    cudaGetSymbolAddress((void**)&qb,  g_qh);
    cudaGetSymbolAddress((void**)&kb,  g_kh);
    cudaGetSymbolAddress((void**)&vb,  g_vh);
    cudaGetSymbolAddress((void**)&kgb, g_kgh);
    cudaGetSymbolAddress((void**)&vgb, g_vgh);
    cudaGetSymbolAddress((void**)&qgb, g_qgh);

    cudaFuncSetAttribute(mma_gemm6,    cudaFuncAttributeMaxDynamicSharedMemorySize, SMT);
    cudaFuncSetAttribute(mma_gemm_out, cudaFuncAttributeMaxDynamicSharedMemorySize, SMT);
    cudaFuncSetAttribute(attn_merged,  cudaFuncAttributeMaxDynamicSharedMemorySize, LA_SMEM);

    // launch 0: weight fp32->fp16 converts
    W7 w7;
    w7.w[0] = Wq; w7.w[1] = Wk; w7.w[2] = Wv; w7.w[3] = Wkg;
    w7.w[4] = Wvg; w7.w[5] = Wqg; w7.w[6] = Wo;
    k_cvt_w<<<dim3((DD * DD / 4 + 255) / 256, 7), 256>>>(w7);

    // launch 1: x fp32->fp16 convert (keeps (S,B,D) layout)
    const int ntot = BB * SS * DD;
    k_cvt_x<<<(ntot / 4 + 255) / 256, 256>>>(query);

    // launch 2: 6 batched GEMMs (4-stage, single barrier per chunk)
    Gemm6 p6;
    p6.bias[0] = bq;  p6.out[0] = qb;  p6.scale[0] = QSCALE;
    p6.bias[1] = bk;  p6.out[1] = kb;  p6.scale[1] = 1.0f;
    p6.bias[2] = bv;  p6.out[2] = vb;  p6.scale[2] = 1.0f;
    p6.bias[3] = bkg; p6.out[3] = kgb; p6.scale[3] = 1.0f;
    p6.bias[4] = bvg; p6.out[4] = vgb; p6.scale[4] = 1.0f;
    p6.bias[5] = bqg; p6.out[5] = qgb; p6.scale[5] = QSCALE;
    mma_gemm6<<<dim3(6, 64, 6), 256, SMT>>>(p6);

    // launch 3: merged local + global attention (PROFILE SLOT)
    attn_merged<<<dim3(64, HH, BB), 256, LA_SMEM>>>(mask);

    // launch 4: combine global partials
    gattn_combine_kernel<<<(BB * HH * GG + 255) / 256, 256>>>();

    // launch 5: final GEMM
    mma_gemm_out<<<dim3(6, 64), 256, SMT>>>(bo, out);
}

// round 14
// speedup vs baseline: 1.5429x; 1.5289x over previous
#include <cuda_runtime.h>
#include <cuda_fp16.h>
#include <math.h>
#include <cstdint>

// Problem constants
#define BB 2
#define SS 4096
#define DD 768
#define HH 12
#define GG 64
#define HD 64
#define WW 256
#define NCC 16
#define NHEADS_S ((size_t)BB * HH * SS * HD)   // 6291456
#define QSCALE (0.125f * 1.4426950408889634f)  // fold log2e: softmax in exp2 domain

// ---------------- scratch (static device globals; no allocation) ----------------
__device__ __half g_xh  [(size_t)BB * SS * DD];      // x fp16, SAME (S,B,D) order as input
__device__ __half g_w16 [7][(size_t)DD * DD];        // W fp16, un-transposed (k,n)
__device__ __half g_qh  [NHEADS_S];                  // [b][h][s][hd], scaled by QSCALE
__device__ __half g_kh  [NHEADS_S];
__device__ __half g_vh  [NHEADS_S];
__device__ __half g_kgh [NHEADS_S];
__device__ __half g_vgh [NHEADS_S];
__device__ __half g_qgh [(size_t)BB * HH * GG * HD];
__device__ __half g_xatth[(size_t)BB * SS * DD];     // attention out, row-major (b,s,d)
__device__ float g_pm   [(size_t)BB * HH * GG * 64];
__device__ float g_pl   [(size_t)BB * HH * GG * 64];
__device__ float g_pacc [(size_t)BB * HH * GG * 64 * HD];

// ---------------- helpers ----------------
__device__ __forceinline__ uint32_t smem_u32(const void* p) {
    uint32_t a;
    asm("{ .reg .u64 t; cvta.to.shared.u64 t, %1; cvt.u32.u64 %0, t; }" : "=r"(a) : "l"(p));
    return a;
}
__device__ __forceinline__ uint32_t packh2(float a, float b) {
    __half2 h = __floats2half2_rn(a, b);
    return *reinterpret_cast<uint32_t*>(&h);
}
// 2^x on the FMA pipe: magic round-to-nearest, degree-4 poly on [-0.5, 0.5]
__device__ __forceinline__ float fexp2(float x) {
    float t = fmaxf(x, -125.0f);
    float r = t + 12582912.0f;
    float fi = r - 12582912.0f;
    float f = t - fi;
    int n = __float_as_int(r) - 0x4B400000;
    float p = 9.61812911e-3f;
    p = fmaf(p, f, 5.55041087e-2f);
    p = fmaf(p, f, 2.40226507e-1f);
    p = fmaf(p, f, 6.93147180e-1f);
    p = fmaf(p, f, 1.0f);
    return __int_as_float((n + 127) << 23) * p;
}
#define CP_ASYNC16(saddr, gptr) \
    asm volatile("cp.async.cg.shared.global [%0], [%1], 16;" :: "r"(saddr), "l"(gptr))
#define CP_COMMIT() asm volatile("cp.async.commit_group;" ::: "memory")
#define CP_WAIT(N)  asm volatile("cp.async.wait_group %0;" :: "n"(N) : "memory")

#define MMA_F16(d, a, b0v, b1v) \
    asm volatile( \
        "mma.sync.aligned.m16n8k16.row.col.f32.f16.f16.f32 " \
        "{%0,%1,%2,%3}, {%4,%5,%6,%7}, {%8,%9}, {%0,%1,%2,%3};" \
        : "+f"((d)[0]), "+f"((d)[1]), "+f"((d)[2]), "+f"((d)[3]) \
        : "r"((a)[0]), "r"((a)[1]), "r"((a)[2]), "r"((a)[3]), \
          "r"(b0v), "r"(b1v))

#define LDSM_X4(r0, r1, r2, r3, addr) \
    asm volatile("ldmatrix.sync.aligned.m8n8.x4.shared.b16 {%0,%1,%2,%3}, [%4];" \
                 : "=r"(r0), "=r"(r1), "=r"(r2), "=r"(r3) : "r"(addr))
#define LDSM_X4_T(r0, r1, r2, r3, addr) \
    asm volatile("ldmatrix.sync.aligned.m8n8.x4.trans.shared.b16 {%0,%1,%2,%3}, [%4];" \
                 : "=r"(r0), "=r"(r1), "=r"(r2), "=r"(r3) : "r"(addr))

// ---------------- elementwise fp32 -> fp16 converts (no transposes) ----------------
__global__ void k_cvt_x(const float* __restrict__ src) {
    size_t t = ((size_t)blockIdx.x * blockDim.x + threadIdx.x) * 4;
    if (t >= (size_t)BB * SS * DD) return;
    float4 v = *(const float4*)(src + t);
    *(uint32_t*)&g_xh[t]     = packh2(v.x, v.y);
    *(uint32_t*)&g_xh[t + 2] = packh2(v.z, v.w);
}
struct W7 { const float* w[7]; };
__global__ void k_cvt_w(W7 p) {
    const float* src = p.w[blockIdx.y];
    __half* dst = g_w16[blockIdx.y];
    size_t t = ((size_t)blockIdx.x * blockDim.x + threadIdx.x) * 4;
    if (t >= (size_t)DD * DD) return;
    float4 v = *(const float4*)(src + t);
    *(uint32_t*)&dst[t]     = packh2(v.x, v.y);
    *(uint32_t*)&dst[t + 2] = packh2(v.z, v.w);
}

// ---------------- fp16 mma.sync GEMM core (round-11: 128x128, 256 thr, trans-B, 3-stage) ----------------
#define OPA 10240                 // A bytes per stage (128*80)
#define BSTR 272                  // B row stride bytes
#define STG 19456                 // stage bytes (10240 + 8704, padded)
#define SMT (3 * STG)             // 58368 (dynamic)

__device__ __forceinline__ void gemm_core_h(
    const __half* __restrict__ X, const __half* __restrict__ Wm,
    const float* __restrict__ bias, float* __restrict__ OutF, __half* __restrict__ OutH,
    int in_mode, int out_mode, float scale, char* smem, int m0, int n0)
{
    const uint32_t sbase = smem_u32(smem);
    const int tid = threadIdx.x;
    const int wid = tid >> 5, lane = tid & 31;
    const int wm = (wid >> 2) * 64;
    const int wn = (wid & 3) * 32;
    const int lr = lane >> 2;
    const int lc = lane & 3;
    const int l16 = lane & 15, lh = lane >> 4;
    const int l8 = lane & 7, lb = (lane >> 3) & 1;

    const __half* arow[2];
    const __half* brow[2];
    uint32_t dstoA[2], dstoB[2];
#pragma unroll
    for (int i = 0; i < 2; i++) {
        int li = i * 256 + tid;
        {   // A
            int row = li >> 2, col4 = li & 3;
            int gr = m0 + row;
            int grow;
            if (in_mode == 0)      grow = (gr & 4095) * 2 + (gr >> 12);
            else if (in_mode == 1) grow = (gr & 63) * 2 + (gr >> 6);
            else                   grow = gr;
            arow[i]  = X + (size_t)grow * 768 + col4 * 8;
            dstoA[i] = (uint32_t)(row * 80 + col4 * 16);
        }
        {   // B: row = k (0..31), col16 = n/8 (0..15)
            int row = li >> 4, col16 = li & 15;
            brow[i]  = Wm + (size_t)row * 768 + n0 + col16 * 8;
            dstoB[i] = (uint32_t)(OPA + row * BSTR + col16 * 16);
        }
    }

    float acc[4][4][4];
#pragma unroll
    for (int mt = 0; mt < 4; mt++)
#pragma unroll
        for (int nt = 0; nt < 4; nt++)
#pragma unroll
            for (int e = 0; e < 4; e++) acc[mt][nt][e] = 0.f;

    auto issue = [&](int cc) {
        const int kn = cc * 32;
        const uint32_t st = sbase + (uint32_t)(cc % 3) * STG;
#pragma unroll
        for (int i = 0; i < 2; i++) {
            CP_ASYNC16(st + dstoA[i], arow[i] + kn);
            CP_ASYNC16(st + dstoB[i], brow[i] + (size_t)kn * 768);
        }
        CP_COMMIT();
    };

    issue(0);
    issue(1);

    for (int c = 0; c < 24; c++) {
        CP_WAIT(1);
        __syncthreads();
        if (c + 2 < 24) issue(c + 2);

        const uint32_t abase = sbase + (uint32_t)(c % 3) * STG;
        const uint32_t bbase = abase + OPA;

#pragma unroll
        for (int ks = 0; ks < 2; ks++) {
            const uint32_t koff = (uint32_t)(ks * 16 + lh * 8) * 2;
            uint32_t af[4][4];
#pragma unroll
            for (int mt = 0; mt < 4; mt++)
                LDSM_X4(af[mt][0], af[mt][1], af[mt][2], af[mt][3],
                        abase + (uint32_t)(wm + mt * 16 + l16) * 80 + koff);
            uint32_t bf[2][4];
#pragma unroll
            for (int g2 = 0; g2 < 2; g2++) {
                int krow = ks * 16 + l8 + lb * 8;
                int ncol = wn + g2 * 16 + lh * 8;
                LDSM_X4_T(bf[g2][0], bf[g2][1], bf[g2][2], bf[g2][3],
                          bbase + (uint32_t)(krow * BSTR + ncol * 2));
            }
#pragma unroll
            for (int mt = 0; mt < 4; mt++)
#pragma unroll
                for (int g2 = 0; g2 < 2; g2++) {
                    MMA_F16(acc[mt][2 * g2],     af[mt], bf[g2][0], bf[g2][1]);
                    MMA_F16(acc[mt][2 * g2 + 1], af[mt], bf[g2][2], bf[g2][3]);
                }
        }
    }

#pragma unroll
    for (int mt = 0; mt < 4; mt++) {
#pragma unroll
        for (int half = 0; half < 2; half++) {
            const int rr = m0 + wm + mt * 16 + lr + half * 8;
#pragma unroll
            for (int nt = 0; nt < 4; nt++) {
                const int nn = n0 + wn + nt * 8 + lc * 2;
                float v0 = (acc[mt][nt][half * 2 + 0] + bias[nn])     * scale;
                float v1 = (acc[mt][nt][half * 2 + 1] + bias[nn + 1]) * scale;
                if (out_mode == 1) {
                    int bb = rr >> 12, ss = rr & 4095;
                    *(float2*)(OutF + ((size_t)ss * BB + bb) * DD + nn) = make_float2(v0, v1);
                } else if (out_mode == 0) {
                    int bb = rr >> 12, ss = rr & 4095;
                    int h = nn >> 6, hd0 = nn & 63;
                    *(uint32_t*)(OutH + ((((size_t)bb * HH + h) * SS + ss) * 64 + hd0)) = packh2(v0, v1);
                } else {
                    int bb = rr >> 6, gg2 = rr & 63;
                    int h = nn >> 6, hd0 = nn & 63;
                    *(uint32_t*)(OutH + ((((size_t)bb * HH + h) * GG + gg2) * 64 + hd0)) = packh2(v0, v1);
                }
            }
        }
    }
}

struct Gemm6 { const float* bias[6]; __half* out[6]; float scale[6]; };
__global__ __launch_bounds__(256, 2)
void mma_gemm6(Gemm6 p)
{
    extern __shared__ char smem[];
    const int z = blockIdx.z;
    if (z == 5) {
        if (blockIdx.y != 0) return;
        gemm_core_h(g_xh, g_w16[5], p.bias[5], nullptr, p.out[5], 1, 2, p.scale[5], smem,
                    0, blockIdx.x * 128);
    } else {
        gemm_core_h(g_xh, g_w16[z], p.bias[z], nullptr, p.out[z], 0, 0, p.scale[z], smem,
                    blockIdx.y * 128, blockIdx.x * 128);
    }
}
__global__ __launch_bounds__(256, 2)
void mma_gemm_out(const float* __restrict__ bias, float* __restrict__ Out)
{
    extern __shared__ char smem[];
    gemm_core_h(g_xatth, g_w16[6], bias, Out, nullptr, 2, 1, 1.0f, smem,
                blockIdx.y * 128, blockIdx.x * 128);
}

// ---------------- merged local + global attention (unchanged from round 11) ----------------
#define KSTR 72
#define ST_KV 18432
#define L_OK  (3 * ST_KV)                // 55296
#define L_TCL (L_OK + 704)               // 56000
#define LA_SMEM 56320

__device__ void local_attn_body(char* sm, const int* __restrict__ mask)
{
    const uint32_t sbase = smem_u32(sm);
    unsigned char* okarr = (unsigned char*)(sm + L_OK);
    int* tclean = (int*)(sm + L_TCL);

    const int c = blockIdx.x >> 1, h = blockIdx.y, b = blockIdx.z;
    const int rhalf = blockIdx.x & 1;
    const int i0 = rhalf * 128;
    const int tid = threadIdx.x, wid = tid >> 5, lane = tid & 31;
    const int lr = lane >> 2, lc = lane & 3;
    const int l8 = lane & 7, lb = (lane >> 3) & 1, lh = lane >> 4;
    const size_t bh = (size_t)b * HH + h;
    const int s0 = c * WW + i0;
    const int tlo = rhalf * 2;
    const int bandlo = (c - 1) * WW + tlo * 64;

    for (int j = tid; j < 704; j += 256) {
        int ok;
        if (j < 64) ok = 1;
        else {
            int p = bandlo + (j - 64);
            ok = (p >= 0 && p < SS && mask[b * SS + p] == 0) ? 1 : 0;
        }
        okarr[j] = (unsigned char)ok;
    }
    __syncthreads();
    if (tid < 10) {
        const uint32_t* w = (const uint32_t*)(okarr + 64 + tid * 64);
        uint32_t allv = 0xFFFFFFFFu;
#pragma unroll
        for (int q4 = 0; q4 < 16; q4++) allv &= w[q4];
        tclean[tid] = (allv == 0x01010101u) ? 1 : 0;
    }

    uint32_t qa[4][4];
    {
        const __half* qb2 = g_qh + (bh * SS + s0 + wid * 16) * 64;
#pragma unroll
        for (int kk = 0; kk < 4; kk++) {
            qa[kk][0] = *(const uint32_t*)&qb2[(lr)     * 64 + kk * 16 + 2 * lc];
            qa[kk][1] = *(const uint32_t*)&qb2[(lr + 8) * 64 + kk * 16 + 2 * lc];
            qa[kk][2] = *(const uint32_t*)&qb2[(lr)     * 64 + kk * 16 + 8 + 2 * lc];
            qa[kk][3] = *(const uint32_t*)&qb2[(lr + 8) * 64 + kk * 16 + 8 + 2 * lc];
        }
    }

    float o[8][4];
#pragma unroll
    for (int nt = 0; nt < 8; nt++)
#pragma unroll
        for (int e = 0; e < 4; e++) o[nt][e] = 0.f;
    float mrun = -1e30f;
    float lr0 = 0.f, lr1 = 0.f;

    const __half* kbase = g_kh + bh * SS * 64;
    const __half* vbase = g_vh + bh * SS * 64;
    const int wbase = i0 + wid * 16;
    const int irelA = wbase + lr;
    const int irelB = irelA + 8;

    auto issue_tile = [&](int ti) {
        const int pbase = (ti == 0) ? 0 : bandlo + (ti - 1) * 64;
        const uint32_t kdst = sbase + (uint32_t)((ti % 3) * ST_KV);
        const uint32_t vdst = kdst + 9216;
#pragma unroll
        for (int i = 0; i < 4; i++) {
            int li = i * 256 + tid;
            int op = li >> 9;
            int rem = li & 511;
            int row = rem >> 3, ch = rem & 7;
            int p = pbase + row;
            p = (p < 0) ? 0 : ((p >= SS) ? SS - 1 : p);
            const __half* src = (op ? vbase : kbase) + (size_t)p * 64 + ch * 8;
            uint32_t dst = (op ? vdst : kdst) + (uint32_t)(row * (KSTR * 2) + ch * 16);
            CP_ASYNC16(dst, src);
        }
        CP_COMMIT();
    };

    issue_tile(0);
    issue_tile(1);

    for (int ti = 0; ti < 11; ti++) {
        CP_WAIT(1);
        __syncthreads();
        if (ti + 2 < 11) issue_tile(ti + 2);

        if (ti > 0) {
            const int jbase = (tlo + ti - 1) * 64;
            if (jbase + 63 < wbase || jbase > wbase + 15 + 2 * WW) continue;
        }

        const uint32_t kbuf = sbase + (uint32_t)((ti % 3) * ST_KV);
        const uint32_t vbuf = kbuf + 9216;

        float cs[8][4];
#pragma unroll
        for (int nt = 0; nt < 8; nt++)
#pragma unroll
            for (int e = 0; e < 4; e++) cs[nt][e] = 0.f;
#pragma unroll
        for (int kk = 0; kk < 4; kk++) {
#pragma unroll
            for (int g4 = 0; g4 < 4; g4++) {
                uint32_t r0, r1, r2, r3;
                int key = g4 * 16 + l8 + lb * 8;
                int dim = kk * 16 + lh * 8;
                LDSM_X4(r0, r1, r2, r3, kbuf + (uint32_t)(key * (KSTR * 2) + dim * 2));
                MMA_F16(cs[2 * g4],     qa[kk], r0, r2);
                MMA_F16(cs[2 * g4 + 1], qa[kk], r1, r3);
            }
        }

        if (ti > 0) {
            const int jbase = (tlo + ti - 1) * 64;
            const bool interior = (tclean[ti - 1] != 0) &&
                                  (jbase >= wbase + 15) &&
                                  (jbase + 63 <= wbase + 2 * WW);
            if (!interior) {
                const unsigned char* okp = okarr + 64 + (ti - 1) * 64;
#pragma unroll
                for (int nt = 0; nt < 8; nt++) {
                    int jl = nt * 8 + 2 * lc;
                    int j = jbase + jl;
                    bool o0 = okp[jl] != 0, o1 = okp[jl + 1] != 0;
                    if (!(o0 && j     >= irelA && j     <= irelA + 512)) cs[nt][0] = -1e30f;
                    if (!(o1 && j + 1 >= irelA && j + 1 <= irelA + 512)) cs[nt][1] = -1e30f;
                    if (!(o0 && j     >= irelB && j     <= irelB + 512)) cs[nt][2] = -1e30f;
                    if (!(o1 && j + 1 >= irelB && j + 1 <= irelB + 512)) cs[nt][3] = -1e30f;
                }
            }
        }

        float ml = -1e30f;
#pragma unroll
        for (int nt = 0; nt < 8; nt++)
            ml = fmaxf(ml, fmaxf(fmaxf(cs[nt][0], cs[nt][1]), fmaxf(cs[nt][2], cs[nt][3])));
        ml = fmaxf(ml, __shfl_xor_sync(0xffffffffu, ml, 1));
        ml = fmaxf(ml, __shfl_xor_sync(0xffffffffu, ml, 2));
        ml = fmaxf(ml, __shfl_xor_sync(0xffffffffu, ml, 4));
        ml = fmaxf(ml, __shfl_xor_sync(0xffffffffu, ml, 8));
        ml = fmaxf(ml, __shfl_xor_sync(0xffffffffu, ml, 16));
        if (ml > mrun) {
            float corr = fexp2(mrun - ml);
            mrun = ml;
            lr0 *= corr; lr1 *= corr;
#pragma unroll
            for (int nt = 0; nt < 8; nt++) {
                o[nt][0] *= corr; o[nt][1] *= corr;
                o[nt][2] *= corr; o[nt][3] *= corr;
            }
        }
        float ps0 = 0.f, ps1 = 0.f;
        uint32_t pa[4][4];
#pragma unroll
        for (int nt = 0; nt < 8; nt++) {
            float p0 = fexp2(cs[nt][0] - mrun);
            float p1 = fexp2(cs[nt][1] - mrun);
            float p2 = fexp2(cs[nt][2] - mrun);
            float p3 = fexp2(cs[nt][3] - mrun);
            ps0 += p0 + p1; ps1 += p2 + p3;
            pa[nt >> 1][(nt & 1) * 2 + 0] = packh2(p0, p1);
            pa[nt >> 1][(nt & 1) * 2 + 1] = packh2(p2, p3);
        }
        lr0 += ps0; lr1 += ps1;

#pragma unroll
        for (int kk = 0; kk < 4; kk++) {
#pragma unroll
            for (int g4 = 0; g4 < 4; g4++) {
                uint32_t r0, r1, r2, r3;
                int key = kk * 16 + l8 + lb * 8;
                int dim = g4 * 16 + lh * 8;
                LDSM_X4_T(r0, r1, r2, r3, vbuf + (uint32_t)(key * (KSTR * 2) + dim * 2));
                MMA_F16(o[2 * g4],     pa[kk], r0, r1);
                MMA_F16(o[2 * g4 + 1], pa[kk], r2, r3);
            }
        }
    }

#pragma unroll
    for (int e = 0; e < 2; e++) {
        float ll = e ? lr1 : lr0;
        ll += __shfl_xor_sync(0xffffffffu, ll, 1);
        ll += __shfl_xor_sync(0xffffffffu, ll, 2);
        const float inv = 1.f / ll;
        const int srow = s0 + wid * 16 + lr + 8 * e;
        __half* orow = g_xatth + ((size_t)b * SS + srow) * DD + h * 64;
#pragma unroll
        for (int nt = 0; nt < 8; nt++)
            *(uint32_t*)&orow[nt * 8 + 2 * lc] =
                packh2(o[nt][2 * e] * inv, o[nt][2 * e + 1] * inv);
    }
}

__device__ void gattn_body(char* sm, const int* __restrict__ mask)
{
    __half* kgs = (__half*)sm;
    __half* vgs = (__half*)(sm + ST_KV);
    unsigned char* okg = (unsigned char*)(sm + 2 * ST_KV);

    const int split = blockIdx.x - 32, h = blockIdx.y, b = blockIdx.z;
    const int tid = threadIdx.x, wid = tid >> 5, lane = tid & 31;
    const int lr = lane >> 2, lc = lane & 3;
    const int l8 = lane & 7, lb = (lane >> 3) & 1, lh = lane >> 4;
    const size_t bh = (size_t)b * HH + h;
    const int wr = wid & 3, kh = wid >> 2;
    const int p0 = split * 128;

    {
        const __half* kb2 = g_kgh + (bh * SS + p0) * 64;
        const __half* vb2 = g_vgh + (bh * SS + p0) * 64;
        const uint32_t kdst = smem_u32(kgs);
        const uint32_t vdst = smem_u32(vgs);
#pragma unroll
        for (int i = 0; i < 8; i++) {
            int li = i * 256 + tid;
            int op = li >> 10;
            int rem = li & 1023;
            int row = rem >> 3, ch = rem & 7;
            const __half* src = (op ? vb2 : kb2) + (size_t)row * 64 + ch * 8;
            uint32_t dst = (op ? vdst : kdst) + (uint32_t)(row * (KSTR * 2) + ch * 16);
            CP_ASYNC16(dst, src);
        }
        CP_COMMIT();
        if (tid < 128) okg[tid] = (mask[b * SS + p0 + tid] <= 0) ? 1 : 0;
        CP_WAIT(0);
        __syncthreads();
    }

    uint32_t qa[4][4];
    {
        const __half* qb2 = g_qgh + (bh * GG + wr * 16) * 64;
#pragma unroll
        for (int kk = 0; kk < 4; kk++) {
            qa[kk][0] = *(const uint32_t*)&qb2[(lr)     * 64 + kk * 16 + 2 * lc];
            qa[kk][1] = *(const uint32_t*)&qb2[(lr + 8) * 64 + kk * 16 + 2 * lc];
            qa[kk][2] = *(const uint32_t*)&qb2[(lr)     * 64 + kk * 16 + 8 + 2 * lc];
            qa[kk][3] = *(const uint32_t*)&qb2[(lr + 8) * 64 + kk * 16 + 8 + 2 * lc];
        }
    }

    const uint32_t kbuf = smem_u32(kgs) + (uint32_t)(kh * 64 * KSTR * 2);
    const uint32_t vbuf = smem_u32(vgs) + (uint32_t)(kh * 64 * KSTR * 2);

    float cs[8][4];
#pragma unroll
    for (int nt = 0; nt < 8; nt++)
#pragma unroll
        for (int e = 0; e < 4; e++) cs[nt][e] = 0.f;
#pragma unroll
    for (int kk = 0; kk < 4; kk++) {
#pragma unroll
        for (int g4 = 0; g4 < 4; g4++) {
            uint32_t r0, r1, r2, r3;
            int key = g4 * 16 + l8 + lb * 8;
            int dim = kk * 16 + lh * 8;
            LDSM_X4(r0, r1, r2, r3, kbuf + (uint32_t)(key * (KSTR * 2) + dim * 2));
            MMA_F16(cs[2 * g4],     qa[kk], r0, r2);
            MMA_F16(cs[2 * g4 + 1], qa[kk], r1, r3);
        }
    }
#pragma unroll
    for (int nt = 0; nt < 8; nt++) {
        int jl = kh * 64 + nt * 8 + 2 * lc;
        if (!okg[jl])     { cs[nt][0] = -1e30f; cs[nt][2] = -1e30f; }
        if (!okg[jl + 1]) { cs[nt][1] = -1e30f; cs[nt][3] = -1e30f; }
    }
    float ml0 = -1e30f, ml1 = -1e30f;
#pragma unroll
    for (int nt = 0; nt < 8; nt++) {
        ml0 = fmaxf(ml0, fmaxf(cs[nt][0], cs[nt][1]));
        ml1 = fmaxf(ml1, fmaxf(cs[nt][2], cs[nt][3]));
    }
    ml0 = fmaxf(ml0, __shfl_xor_sync(0xffffffffu, ml0, 1));
    ml0 = fmaxf(ml0, __shfl_xor_sync(0xffffffffu, ml0, 2));
    ml1 = fmaxf(ml1, __shfl_xor_sync(0xffffffffu, ml1, 1));
    ml1 = fmaxf(ml1, __shfl_xor_sync(0xffffffffu, ml1, 2));
    float ps0 = 0.f, ps1 = 0.f;
    uint32_t pa[4][4];
#pragma unroll
    for (int nt = 0; nt < 8; nt++) {
        float pp0 = fexp2(cs[nt][0] - ml0);
        float pp1 = fexp2(cs[nt][1] - ml0);
        float pp2 = fexp2(cs[nt][2] - ml1);
        float pp3 = fexp2(cs[nt][3] - ml1);
        ps0 += pp0 + pp1; ps1 += pp2 + pp3;
        pa[nt >> 1][(nt & 1) * 2 + 0] = packh2(pp0, pp1);
        pa[nt >> 1][(nt & 1) * 2 + 1] = packh2(pp2, pp3);
    }
    ps0 += __shfl_xor_sync(0xffffffffu, ps0, 1);
    ps0 += __shfl_xor_sync(0xffffffffu, ps0, 2);
    ps1 += __shfl_xor_sync(0xffffffffu, ps1, 1);
    ps1 += __shfl_xor_sync(0xffffffffu, ps1, 2);

    float o[8][4];
#pragma unroll
    for (int nt = 0; nt < 8; nt++)
#pragma unroll
        for (int e = 0; e < 4; e++) o[nt][e] = 0.f;
#pragma unroll
    for (int kk = 0; kk < 4; kk++) {
#pragma unroll
        for (int g4 = 0; g4 < 4; g4++) {
            uint32_t r0, r1, r2, r3;
            int key = kk * 16 + l8 + lb * 8;
            int dim = g4 * 16 + lh * 8;
            LDSM_X4_T(r0, r1, r2, r3, vbuf + (uint32_t)(key * (KSTR * 2) + dim * 2));
            MMA_F16(o[2 * g4],     pa[kk], r0, r1);
            MMA_F16(o[2 * g4 + 1], pa[kk], r2, r3);
        }
    }

    const int pid = split * 2 + kh;
#pragma unroll
    for (int e = 0; e < 2; e++) {
        const int grow = wr * 16 + lr + 8 * e;
        const size_t idx = (bh * GG + grow) * 64 + pid;
        if (lc == 0) {
            g_pm[idx] = e ? ml1 : ml0;
            g_pl[idx] = e ? ps1 : ps0;
        }
        float* ap = g_pacc + idx * 64;
#pragma unroll
        for (int nt = 0; nt < 8; nt++)
            *(float2*)&ap[nt * 8 + 2 * lc] = make_float2(o[nt][2 * e], o[nt][2 * e + 1]);
    }
}

__global__ __launch_bounds__(256, 2)
void attn_merged(const int* __restrict__ mask)
{
    extern __shared__ char sm[];
    if (blockIdx.x < 32) local_attn_body(sm, mask);
    else                 gattn_body(sm, mask);
}

// ---------------- parallel combine: one warp per output row ----------------
// grid 384 x 128 thr (4 warps/CTA) = 1536 warps = one per (b,h,g) row.
__global__ __launch_bounds__(128)
void gattn_combine_kernel(void)
{
    const int rid = blockIdx.x * 4 + (threadIdx.x >> 5);
    const int lane = threadIdx.x & 31;
    if (rid >= BB * HH * GG) return;

    const float* pmrow = g_pm + (size_t)rid * 64;
    const float* plrow = g_pl + (size_t)rid * 64;

    // row max over 64 partials (each lane covers 2)
    float pm0 = pmrow[lane], pm1 = pmrow[lane + 32];
    float M = fmaxf(pm0, pm1);
#pragma unroll
    for (int s = 16; s > 0; s >>= 1)
        M = fmaxf(M, __shfl_xor_sync(0xffffffffu, M, s));

    // per-lane weights for partials lane and lane+32
    float w0 = fexp2(pm0 - M);
    float w1 = fexp2(pm1 - M);

    // L = sum w_p * l_p
    float L = plrow[lane] * w0 + plrow[lane + 32] * w1;
#pragma unroll
    for (int s = 16; s > 0; s >>= 1)
        L += __shfl_xor_sync(0xffffffffu, L, s);

    // acc: lane handles dims 2*lane, 2*lane+1; weight broadcast via shfl
    float a0 = 0.f, a1 = 0.f;
    const float* ap = g_pacc + (size_t)rid * 64 * 64 + 2 * lane;
    for (int p = 0; p < 64; p++) {
        float w = __shfl_sync(0xffffffffu, (p < 32) ? w0 : w1, p & 31);
        float2 v = *(const float2*)(ap + (size_t)p * 64);
        a0 = fmaf(w, v.x, a0);
        a1 = fmaf(w, v.y, a1);
    }

    const float inv = 1.f / L;
    const int bh = rid >> 6, g = rid & 63;
    const int b = bh / HH, h = bh % HH;
    __half* orow = g_xatth + ((size_t)b * SS + g) * DD + h * 64;
    *(uint32_t*)&orow[2 * lane] = packh2(a0 * inv, a1 * inv);
}

// ---------------- launcher ----------------
extern "C" void kernel_launch(void* const* d_in, const int* in_sizes, int n_in,
                              void* d_out, int out_size)
{
    (void)in_sizes; (void)n_in; (void)out_size;
    const float* query = (const float*)d_in[0];
    const int*   mask  = (const int*)d_in[1];
    const float* Wq  = (const float*)d_in[2];
    const float* bq  = (const float*)d_in[3];
    const float* Wk  = (const float*)d_in[4];
    const float* bk  = (const float*)d_in[5];
    const float* Wv  = (const float*)d_in[6];
    const float* bv  = (const float*)d_in[7];
    const float* Wqg = (const float*)d_in[8];
    const float* bqg = (const float*)d_in[9];
    const float* Wkg = (const float*)d_in[10];
    const float* bkg = (const float*)d_in[11];
    const float* Wvg = (const float*)d_in[12];
    const float* bvg = (const float*)d_in[13];
    const float* Wo  = (const float*)d_in[14];
    const float* bo  = (const float*)d_in[15];
    float* out = (float*)d_out;

    __half *qb, *kb, *vb, *kgb, *vgb, *qgb;
    cudaGetSymbolAddress((void**)&qb,  g_qh);
    cudaGetSymbolAddress((void**)&kb,  g_kh);
    cudaGetSymbolAddress((void**)&vb,  g_vh);
    cudaGetSymbolAddress((void**)&kgb, g_kgh);
    cudaGetSymbolAddress((void**)&vgb, g_vgh);
    cudaGetSymbolAddress((void**)&qgb, g_qgh);

    cudaFuncSetAttribute(mma_gemm6,    cudaFuncAttributeMaxDynamicSharedMemorySize, SMT);
    cudaFuncSetAttribute(mma_gemm_out, cudaFuncAttributeMaxDynamicSharedMemorySize, SMT);
    cudaFuncSetAttribute(attn_merged,  cudaFuncAttributeMaxDynamicSharedMemorySize, LA_SMEM);

    // launch 0: weight fp32->fp16 converts
    W7 w7;
    w7.w[0] = Wq; w7.w[1] = Wk; w7.w[2] = Wv; w7.w[3] = Wkg;
    w7.w[4] = Wvg; w7.w[5] = Wqg; w7.w[6] = Wo;
    k_cvt_w<<<dim3((DD * DD / 4 + 255) / 256, 7), 256>>>(w7);

    // launch 1: x fp32->fp16 convert (keeps (S,B,D) layout)
    const int ntot = BB * SS * DD;
    k_cvt_x<<<(ntot / 4 + 255) / 256, 256>>>(query);

    // launch 2: 6 batched GEMMs (round-11 3-stage config)
    Gemm6 p6;
    p6.bias[0] = bq;  p6.out[0] = qb;  p6.scale[0] = QSCALE;
    p6.bias[1] = bk;  p6.out[1] = kb;  p6.scale[1] = 1.0f;
    p6.bias[2] = bv;  p6.out[2] = vb;  p6.scale[2] = 1.0f;
    p6.bias[3] = bkg; p6.out[3] = kgb; p6.scale[3] = 1.0f;
    p6.bias[4] = bvg; p6.out[4] = vgb; p6.scale[4] = 1.0f;
    p6.bias[5] = bqg; p6.out[5] = qgb; p6.scale[5] = QSCALE;
    mma_gemm6<<<dim3(6, 64, 6), 256, SMT>>>(p6);

    // launch 3: merged local + global attention (PROFILE SLOT)
    attn_merged<<<dim3(64, HH, BB), 256, LA_SMEM>>>(mask);

    // launch 4: combine global partials (warp-per-row, 384 CTAs)
    gattn_combine_kernel<<<384, 128>>>();

    // launch 5: final GEMM
    mma_gemm_out<<<dim3(6, 64), 256, SMT>>>(bo, out);
}